// round 6
// baseline (speedup 1.0000x reference)
#include <cuda_runtime.h>
#include <cuda_bf16.h>
#include <cstdint>

#define B 16
#define N 4096
#define C 64
#define P 1024      // NPOINT
#define S 32        // NSAMPLE
#define CIN0 67
#define C1 64
#define C2 64
#define C3 128
#define CNT (B*P*S) // 524288 samples per channel for BN

#define OFF_NEWXYZ 0
#define OFF_NEWPTS (B*P*3)                 // 49152
#define OFF_IDX    (B*P*3 + B*P*C3)        // 2146304

typedef unsigned long long ull;

// ---------------- f32x2 packed helpers (sm_103a) -----------------------------
__device__ __forceinline__ ull pk2(float x) {
    ull r; asm("mov.b64 %0, {%1, %1};" : "=l"(r) : "f"(x)); return r;
}
__device__ __forceinline__ ull pack2(float lo, float hi) {
    ull r; asm("mov.b64 %0, {%1, %2};" : "=l"(r) : "f"(lo), "f"(hi)); return r;
}
__device__ __forceinline__ ull fma2(ull a, ull b, ull c) {
    ull d; asm("fma.rn.f32x2 %0, %1, %2, %3;" : "=l"(d) : "l"(a), "l"(b), "l"(c)); return d;
}
__device__ __forceinline__ ull mul2(ull a, ull b) {
    ull d; asm("mul.rn.f32x2 %0, %1, %2;" : "=l"(d) : "l"(a), "l"(b)); return d;
}
__device__ __forceinline__ ull add2(ull a, ull b) {
    ull d; asm("add.rn.f32x2 %0, %1, %2;" : "=l"(d) : "l"(a), "l"(b)); return d;
}
__device__ __forceinline__ void upk(ull a, float& lo, float& hi) {
    asm("mov.b64 {%0, %1}, %2;" : "=f"(lo), "=f"(hi) : "l"(a));
}
__device__ __forceinline__ ull shfl64(ull v, int off) {
    return __shfl_xor_sync(0xffffffffu, v, off);
}

// ---------------- mma.sync bf16 (baseline sm_80+ PTX, works on sm_103) -------
__device__ __forceinline__ void mma_bf16(float* d, const uint32_t* a, uint32_t b0, uint32_t b1) {
    asm volatile("mma.sync.aligned.m16n8k16.row.col.f32.bf16.bf16.f32 "
        "{%0,%1,%2,%3}, {%4,%5,%6,%7}, {%8,%9}, {%0,%1,%2,%3};"
        : "+f"(d[0]), "+f"(d[1]), "+f"(d[2]), "+f"(d[3])
        : "r"(a[0]), "r"(a[1]), "r"(a[2]), "r"(a[3]), "r"(b0), "r"(b1));
}

// split fp32 pair into bf16x2 (hi) and bf16x2 (residual lo); first arg = low half
__device__ __forceinline__ void split2(float a, float b, uint32_t& hi, uint32_t& lo) {
    __nv_bfloat16 ha = __float2bfloat16_rn(a);
    __nv_bfloat16 hb = __float2bfloat16_rn(b);
    __nv_bfloat162 hh = __halves2bfloat162(ha, hb);
    hi = *reinterpret_cast<uint32_t*>(&hh);
    float la = a - __bfloat162float(ha);
    float lb = b - __bfloat162float(hb);
    __nv_bfloat162 ll = __floats2bfloat162_rn(la, lb);
    lo = *reinterpret_cast<uint32_t*>(&ll);
}

// ---------------- scratch (static device memory; no allocations) ------------
__device__ float g_new_xyz[B*P*3];
__device__ int   g_idx[B*P*S];
// y layout: 16B chunks: [group][chunk 0..15][lane 0..31], chunk = 4 channels
__device__ float g_y1[(size_t)B*P*S*C1];   // 134 MB
__device__ float g_y2[(size_t)B*P*S*C2];   // 134 MB
__device__ float g_max3[(size_t)B*P*C3];   // 8 MB

__device__ float g_sum0[C1], g_sq0[C1];
__device__ float g_sum1[C2], g_sq1[C2];
__device__ float g_sum2[C3], g_sq2[C3];

// ---------------- FPS: one block per batch (also zeroes stats) --------------
#define FPS_T 512
#define FPS_PP (N/FPS_T)   // 8 points per thread = 4 f32x2 pairs
__global__ void fps_kernel(const float* __restrict__ xyz, float* __restrict__ out) {
    extern __shared__ float sm[];
    float* sx = sm; float* sy = sm + N; float* sz = sm + 2*N;
    __shared__ ull skey[2][FPS_T/32];

    const int b = blockIdx.x;
    const int t = threadIdx.x;
    const int lane = t & 31, w = t >> 5;

    if (b == 0) {
        if (t < C1) { g_sum0[t]=0.f; g_sq0[t]=0.f; g_sum1[t]=0.f; g_sq1[t]=0.f; }
        if (t < C3) { g_sum2[t]=0.f; g_sq2[t]=0.f; }
    }

    const float* base = xyz + (size_t)b * N * 3;
    for (int i = t; i < N; i += FPS_T) {
        sx[i] = base[i*3+0]; sy[i] = base[i*3+1]; sz[i] = base[i*3+2];
    }
    __syncthreads();

    // packed pairs: pair jp holds indices (t + 2jp*FPS_T, t + (2jp+1)*FPS_T)
    ull px2[FPS_PP/2], py2[FPS_PP/2], pz2[FPS_PP/2], dd2[FPS_PP/2];
    #pragma unroll
    for (int jp = 0; jp < FPS_PP/2; jp++) {
        int i0 = t + (2*jp)*FPS_T, i1 = i0 + FPS_T;
        px2[jp] = pack2(sx[i0], sx[i1]);
        py2[jp] = pack2(sy[i0], sy[i1]);
        pz2[jp] = pack2(sz[i0], sz[i1]);
        dd2[jp] = pk2(1e10f);
    }

    int far = 0;
    for (int k = 0; k < P; k++) {
        float fx = sx[far], fy = sy[far], fz = sz[far];
        if (t == 0) {
            size_t gk = (size_t)b*P + k;
            g_new_xyz[gk*3+0]=fx; g_new_xyz[gk*3+1]=fy; g_new_xyz[gk*3+2]=fz;
            out[OFF_NEWXYZ + gk*3+0]=fx; out[OFF_NEWXYZ + gk*3+1]=fy; out[OFF_NEWXYZ + gk*3+2]=fz;
        }
        // x - f == x + (-f) exactly in fp
        ull nfx = pk2(-fx), nfy = pk2(-fy), nfz = pk2(-fz);
        float bv = -1.f; int bi = 0x7fffffff;
        #pragma unroll
        for (int jp = 0; jp < FPS_PP/2; jp++) {
            ull dx = add2(px2[jp], nfx);
            ull dy = add2(py2[jp], nfy);
            ull dz = add2(pz2[jp], nfz);
            ull d  = add2(add2(mul2(dx,dx), mul2(dy,dy)), mul2(dz,dz));
            float dlo, dhi, olo, ohi;
            upk(d, dlo, dhi);
            upk(dd2[jp], olo, ohi);
            olo = fminf(olo, dlo);
            ohi = fminf(ohi, dhi);
            dd2[jp] = pack2(olo, ohi);
            int i0 = t + (2*jp)*FPS_T;
            if (olo > bv) { bv = olo; bi = i0; }
            if (ohi > bv) { bv = ohi; bi = i0 + FPS_T; }
        }
        unsigned bvb = __float_as_uint(bv);
        unsigned mb  = __reduce_max_sync(0xffffffffu, bvb);
        unsigned bim = (bvb == mb) ? (unsigned)bi : 0x7fffffffu;
        unsigned bmin = __reduce_min_sync(0xffffffffu, bim);
        if (lane == 0) skey[k & 1][w] = ((ull)mb << 32) | (unsigned)(~bmin);
        __syncthreads();
        ull kb = skey[k & 1][0];
        #pragma unroll
        for (int q = 1; q < FPS_T/32; q++) {
            ull o = skey[k & 1][q];
            if (o > kb) kb = o;
        }
        far = (int)(~(unsigned)kb);
    }
}

// ---------------- Ball query: one warp per center ---------------------------
__global__ void ballq_kernel(const float* __restrict__ xyz, float* __restrict__ out) {
    extern __shared__ float sm[];
    float* sx = sm; float* sy = sm + N; float* sz = sm + 2*N;
    const int b = blockIdx.y;
    const int tid = threadIdx.x;
    const float* base = xyz + (size_t)b * N * 3;
    for (int i = tid; i < N; i += blockDim.x) {
        sx[i] = base[i*3+0]; sy[i] = base[i*3+1]; sz[i] = base[i*3+2];
    }
    __syncthreads();

    const int w = tid >> 5, lane = tid & 31;
    const int p = blockIdx.x * 8 + w;
    const int g = b * P + p;
    const float cx = g_new_xyz[g*3+0], cy = g_new_xyz[g*3+1], cz = g_new_xyz[g*3+2];
    const float R2 = (float)(0.4 * 0.4);

    int cnt = 0, first = -1;
    for (int basei = 0; basei < N; basei += 32) {
        int i = basei + lane;
        float dx = __fsub_rn(cx, sx[i]);
        float dy = __fsub_rn(cy, sy[i]);
        float dz = __fsub_rn(cz, sz[i]);
        float d2 = __fadd_rn(__fadd_rn(__fmul_rn(dx,dx), __fmul_rn(dy,dy)), __fmul_rn(dz,dz));
        bool pred = d2 < R2;
        unsigned m = __ballot_sync(0xffffffffu, pred);
        if (first < 0 && m) first = basei + __ffs(m) - 1;
        int rank = cnt + __popc(m & ((1u << lane) - 1u));
        if (pred && rank < S) {
            g_idx[g*S + rank] = i;
            out[OFF_IDX + g*S + rank] = (float)i;
        }
        cnt += __popc(m);
        if (cnt >= S) break;
    }
    int cntc = cnt < S ? cnt : S;
    if (lane >= cntc) {
        g_idx[g*S + lane] = first;
        out[OFF_IDX + g*S + lane] = (float)first;
    }
}

// =============================================================================
// conv1: mma.sync bf16 GEMM, gather + concat, K=67 padded to 80 (5 k-steps)
// smem: whi @0 (11520), wlo @11520 (11520), zbuf @23040 (4 x 11264),
//       params @68096 (ssum64, ssq64 = 512) -> 68608 total
// z rows: 40 words (80 bf16) per sample, stride 44 words
// =============================================================================
#define CV1_WLO  11520
#define CV1_ZB   23040
#define CV1_PAR  68096
#define CV1_SMEM 68608

__global__ __launch_bounds__(128) void conv1_mma(const float* __restrict__ xyz,
                                                 const float* __restrict__ pts,
                                                 const float* __restrict__ W0) {
    extern __shared__ char smraw[];
    uint32_t* whi = (uint32_t*)(smraw);
    uint32_t* wlo = (uint32_t*)(smraw + CV1_WLO);
    float* ssum = (float*)(smraw + CV1_PAR);
    float* ssq  = ssum + 64;

    const int tid = threadIdx.x, wid = tid >> 5, lane = tid & 31;
    const int q = lane & 3, r0 = lane >> 2;
    const int g = blockIdx.x * 4 + wid;
    const int b = g >> 10;

    // W pairs: wpair[kk][n] = {in[2kk], in[2kk+1]} weights (zero-padded past 66)
    for (int idx = tid; idx < 40*64; idx += 128) {
        int kk = idx >> 6, n = idx & 63;
        float a  = (2*kk     < CIN0) ? W0[(2*kk)*C1 + n]     : 0.f;
        float bq = (2*kk + 1 < CIN0) ? W0[(2*kk+1)*C1 + n]   : 0.f;
        uint32_t hi, lo;
        split2(a, bq, hi, lo);
        whi[kk*72 + n] = hi; wlo[kk*72 + n] = lo;
    }
    if (tid < 64) { ssum[tid] = 0.f; ssq[tid] = 0.f; }
    __syncthreads();

    uint32_t* zhi = (uint32_t*)(smraw + CV1_ZB) + wid*2816;   // [32][44] words
    uint32_t* zlo = zhi + 1408;

    {   // stage A: lane = sample; gather xyz rel + pts, split, zero-pad
        const int j = g_idx[g*S + lane];
        const float* xr = xyz + ((size_t)b*N + j)*3;
        float rx = xr[0] - g_new_xyz[g*3+0];
        float ry = xr[1] - g_new_xyz[g*3+1];
        float rz = xr[2] - g_new_xyz[g*3+2];
        uint32_t hi, lo;
        split2(rx, ry, hi, lo);
        zhi[lane*44 + 0] = hi; zlo[lane*44 + 0] = lo;

        const float4* pr = (const float4*)(pts + ((size_t)b*N + j)*C);
        float carry = rz;
        int kk = 1;
        #pragma unroll
        for (int qq = 0; qq < 16; qq++) {
            float4 v = __ldg(pr + qq);
            split2(carry, v.x, hi, lo);
            zhi[lane*44 + kk] = hi; zlo[lane*44 + kk] = lo; kk++;
            split2(v.y, v.z, hi, lo);
            zhi[lane*44 + kk] = hi; zlo[lane*44 + kk] = lo; kk++;
            carry = v.w;
        }
        split2(carry, 0.f, hi, lo);
        zhi[lane*44 + 33] = hi; zlo[lane*44 + 33] = lo;
        #pragma unroll
        for (int kz = 34; kz < 40; kz++) { zhi[lane*44 + kz] = 0u; zlo[lane*44 + kz] = 0u; }
    }
    __syncwarp();

    float acc[2][8][4];
    #pragma unroll
    for (int mt = 0; mt < 2; mt++)
        #pragma unroll
        for (int nt = 0; nt < 8; nt++)
            #pragma unroll
            for (int e = 0; e < 4; e++) acc[mt][nt][e] = 0.f;

    #pragma unroll
    for (int ks = 0; ks < 5; ks++) {
        uint32_t ah[2][4], al[2][4];
        const int cb = 8*ks + q;
        #pragma unroll
        for (int mt = 0; mt < 2; mt++) {
            int ra = mt*16 + r0, rb = ra + 8;
            ah[mt][0] = zhi[ra*44 + cb];     ah[mt][1] = zhi[rb*44 + cb];
            ah[mt][2] = zhi[ra*44 + cb + 4]; ah[mt][3] = zhi[rb*44 + cb + 4];
            al[mt][0] = zlo[ra*44 + cb];     al[mt][1] = zlo[rb*44 + cb];
            al[mt][2] = zlo[ra*44 + cb + 4]; al[mt][3] = zlo[rb*44 + cb + 4];
        }
        #pragma unroll
        for (int nt = 0; nt < 8; nt++) {
            int wb  = cb*72 + 8*nt + r0;
            uint32_t bh0 = whi[wb], bh1 = whi[wb + 4*72];
            uint32_t bl0 = wlo[wb], bl1 = wlo[wb + 4*72];
            #pragma unroll
            for (int mt = 0; mt < 2; mt++) {
                mma_bf16(acc[mt][nt], ah[mt], bh0, bh1);
                mma_bf16(acc[mt][nt], ah[mt], bl0, bl1);
                mma_bf16(acc[mt][nt], al[mt], bh0, bh1);
            }
        }
    }
    __syncwarp();

    // D -> smem (overlay z buffers), stride 68 words
    float* Ds = (float*)zhi;
    #pragma unroll
    for (int mt = 0; mt < 2; mt++) {
        int ra = mt*16 + r0;
        #pragma unroll
        for (int nt = 0; nt < 8; nt++) {
            int cbb = 8*nt + 2*q;
            *(float2*)(Ds + ra*68 + cbb)     = make_float2(acc[mt][nt][0], acc[mt][nt][1]);
            *(float2*)(Ds + (ra+8)*68 + cbb) = make_float2(acc[mt][nt][2], acc[mt][nt][3]);
        }
    }
    __syncwarp();

    // y1 store in chunk layout: lane = sample
    float4* ydst = (float4*)g_y1 + (size_t)g*512 + lane;
    #pragma unroll
    for (int qq = 0; qq < 16; qq++)
        ydst[qq*32] = *(float4*)(Ds + lane*68 + 4*qq);

    // column stats
    #pragma unroll
    for (int cp = 0; cp < 2; cp++) {
        int c = lane + 32*cp;
        float s = 0.f, sq = 0.f;
        #pragma unroll 8
        for (int ss = 0; ss < 32; ss++) {
            float x = Ds[ss*68 + c];
            s += x; sq += x*x;
        }
        atomicAdd(&ssum[c], s);
        atomicAdd(&ssq[c],  sq);
    }
    __syncthreads();
    if (tid < 64) {
        atomicAdd(&g_sum0[tid], ssum[tid]);
        atomicAdd(&g_sq0[tid],  ssq[tid]);
    }
}

// =============================================================================
// conv2: mma.sync bf16 hi/lo split GEMM [32 x 64] @ [64 x 64] per warp/group
// =============================================================================
#define CV2_WLO   9216
#define CV2_ZB   18432
#define CV2_PAR  55296
#define CV2_SMEM 56320

__global__ __launch_bounds__(128) void conv2_mma(const float* __restrict__ W1,
                                                 const float* __restrict__ g0p,
                                                 const float* __restrict__ be0) {
    extern __shared__ char smraw[];
    uint32_t* whi = (uint32_t*)(smraw);
    uint32_t* wlo = (uint32_t*)(smraw + CV2_WLO);
    float* ssc  = (float*)(smraw + CV2_PAR);
    float* ssh  = ssc + 64;
    float* ssum = ssh + 64;
    float* ssq  = ssum + 64;

    const int tid = threadIdx.x, wid = tid >> 5, lane = tid & 31;
    const int q = lane & 3, r0 = lane >> 2;
    const int g = blockIdx.x * 4 + wid;

    for (int idx = tid; idx < 32*64; idx += 128) {
        int kk = idx >> 6, n = idx & 63;
        uint32_t hi, lo;
        split2(W1[(2*kk)*C2 + n], W1[(2*kk+1)*C2 + n], hi, lo);
        whi[kk*72 + n] = hi; wlo[kk*72 + n] = lo;
    }
    if (tid < 64) {
        const float inv = 1.0f / (float)CNT;
        float m = g_sum0[tid] * inv;
        float v = g_sq0[tid] * inv - m*m;
        float sc = g0p[tid] * rsqrtf(v + 0.001f);
        ssc[tid] = sc; ssh[tid] = be0[tid] - m*sc;
        ssum[tid] = 0.f; ssq[tid] = 0.f;
    }
    __syncthreads();

    uint32_t* zhi = (uint32_t*)(smraw + CV2_ZB) + wid*2304;   // [32][36] words
    uint32_t* zlo = zhi + 1152;

    {   // stage A: lane = sample; BN0 + relu + split
        const float4* xsrc = (const float4*)g_y1 + (size_t)g*512 + lane;
        #pragma unroll
        for (int qq = 0; qq < 16; qq++) {
            float4 v = xsrc[qq*32];
            int c = qq*4;
            float z0 = fmaxf(fmaf(v.x, ssc[c+0], ssh[c+0]), 0.f);
            float z1 = fmaxf(fmaf(v.y, ssc[c+1], ssh[c+1]), 0.f);
            float z2 = fmaxf(fmaf(v.z, ssc[c+2], ssh[c+2]), 0.f);
            float z3 = fmaxf(fmaf(v.w, ssc[c+3], ssh[c+3]), 0.f);
            uint32_t h0, l0, h1, l1;
            split2(z0, z1, h0, l0); split2(z2, z3, h1, l1);
            zhi[lane*36 + 2*qq]     = h0; zhi[lane*36 + 2*qq + 1] = h1;
            zlo[lane*36 + 2*qq]     = l0; zlo[lane*36 + 2*qq + 1] = l1;
        }
    }
    __syncwarp();

    float acc[2][8][4];
    #pragma unroll
    for (int mt = 0; mt < 2; mt++)
        #pragma unroll
        for (int nt = 0; nt < 8; nt++)
            #pragma unroll
            for (int e = 0; e < 4; e++) acc[mt][nt][e] = 0.f;

    #pragma unroll
    for (int ks = 0; ks < 4; ks++) {
        uint32_t ah[2][4], al[2][4];
        const int cb = 8*ks + q;
        #pragma unroll
        for (int mt = 0; mt < 2; mt++) {
            int ra = mt*16 + r0, rb = ra + 8;
            ah[mt][0] = zhi[ra*36 + cb];     ah[mt][1] = zhi[rb*36 + cb];
            ah[mt][2] = zhi[ra*36 + cb + 4]; ah[mt][3] = zhi[rb*36 + cb + 4];
            al[mt][0] = zlo[ra*36 + cb];     al[mt][1] = zlo[rb*36 + cb];
            al[mt][2] = zlo[ra*36 + cb + 4]; al[mt][3] = zlo[rb*36 + cb + 4];
        }
        #pragma unroll
        for (int nt = 0; nt < 8; nt++) {
            int wb  = cb*72 + 8*nt + r0;
            uint32_t bh0 = whi[wb], bh1 = whi[wb + 4*72];
            uint32_t bl0 = wlo[wb], bl1 = wlo[wb + 4*72];
            #pragma unroll
            for (int mt = 0; mt < 2; mt++) {
                mma_bf16(acc[mt][nt], ah[mt], bh0, bh1);
                mma_bf16(acc[mt][nt], ah[mt], bl0, bl1);
                mma_bf16(acc[mt][nt], al[mt], bh0, bh1);
            }
        }
    }
    __syncwarp();

    float* Ds = (float*)zhi;
    #pragma unroll
    for (int mt = 0; mt < 2; mt++) {
        int ra = mt*16 + r0;
        #pragma unroll
        for (int nt = 0; nt < 8; nt++) {
            int cbb = 8*nt + 2*q;
            *(float2*)(Ds + ra*68 + cbb)     = make_float2(acc[mt][nt][0], acc[mt][nt][1]);
            *(float2*)(Ds + (ra+8)*68 + cbb) = make_float2(acc[mt][nt][2], acc[mt][nt][3]);
        }
    }
    __syncwarp();

    float4* ydst = (float4*)g_y2 + (size_t)g*512 + lane;
    #pragma unroll
    for (int qq = 0; qq < 16; qq++)
        ydst[qq*32] = *(float4*)(Ds + lane*68 + 4*qq);

    #pragma unroll
    for (int cp = 0; cp < 2; cp++) {
        int c = lane + 32*cp;
        float s = 0.f, sq = 0.f;
        #pragma unroll 8
        for (int ss = 0; ss < 32; ss++) {
            float x = Ds[ss*68 + c];
            s += x; sq += x*x;
        }
        atomicAdd(&ssum[c], s);
        atomicAdd(&ssq[c],  sq);
    }
    __syncthreads();
    if (tid < 64) {
        atomicAdd(&g_sum1[tid], ssum[tid]);
        atomicAdd(&g_sq1[tid],  ssq[tid]);
    }
}

// =============================================================================
// conv3: mma.sync bf16 GEMM [32 x 64] @ [64 x 128] + stats + max-pool
// =============================================================================
#define CV3_WLO  17408
#define CV3_ZB   34816
#define CV3_PAR  71680
#define CV3_SMEM 73216

__global__ __launch_bounds__(128) void conv3_mma(const float* __restrict__ W2,
                                                 const float* __restrict__ g1p,
                                                 const float* __restrict__ be1) {
    extern __shared__ char smraw[];
    uint32_t* whi = (uint32_t*)(smraw);
    uint32_t* wlo = (uint32_t*)(smraw + CV3_WLO);
    float* ssc   = (float*)(smraw + CV3_PAR);
    float* ssh   = ssc + 64;
    float* ssum2 = ssh + 64;    // [128]
    float* ssq2  = ssum2 + 128; // [128]

    const int tid = threadIdx.x, wid = tid >> 5, lane = tid & 31;
    const int q = lane & 3, r0 = lane >> 2;
    const int g = blockIdx.x * 4 + wid;

    for (int idx = tid; idx < 32*128; idx += 128) {
        int kk = idx >> 7, n = idx & 127;
        uint32_t hi, lo;
        split2(W2[(2*kk)*C3 + n], W2[(2*kk+1)*C3 + n], hi, lo);
        whi[kk*136 + n] = hi; wlo[kk*136 + n] = lo;
    }
    if (tid < 64) {
        const float inv = 1.0f / (float)CNT;
        float m = g_sum1[tid] * inv;
        float v = g_sq1[tid] * inv - m*m;
        float sc = g1p[tid] * rsqrtf(v + 0.001f);
        ssc[tid] = sc; ssh[tid] = be1[tid] - m*sc;
    }
    ssum2[tid] = 0.f; ssq2[tid] = 0.f;
    __syncthreads();

    uint32_t* zhi = (uint32_t*)(smraw + CV3_ZB) + wid*2304;
    uint32_t* zlo = zhi + 1152;

    {   // stage A: BN1 + relu + split from y2
        const float4* xsrc = (const float4*)g_y2 + (size_t)g*512 + lane;
        #pragma unroll
        for (int qq = 0; qq < 16; qq++) {
            float4 v = xsrc[qq*32];
            int c = qq*4;
            float z0 = fmaxf(fmaf(v.x, ssc[c+0], ssh[c+0]), 0.f);
            float z1 = fmaxf(fmaf(v.y, ssc[c+1], ssh[c+1]), 0.f);
            float z2 = fmaxf(fmaf(v.z, ssc[c+2], ssh[c+2]), 0.f);
            float z3 = fmaxf(fmaf(v.w, ssc[c+3], ssh[c+3]), 0.f);
            uint32_t h0, l0, h1, l1;
            split2(z0, z1, h0, l0); split2(z2, z3, h1, l1);
            zhi[lane*36 + 2*qq]     = h0; zhi[lane*36 + 2*qq + 1] = h1;
            zlo[lane*36 + 2*qq]     = l0; zlo[lane*36 + 2*qq + 1] = l1;
        }
    }
    __syncwarp();

    #pragma unroll 1
    for (int ch = 0; ch < 4; ch++) {       // 4 n-chunks of 32 cols
        float acc[2][4][4];
        #pragma unroll
        for (int mt = 0; mt < 2; mt++)
            #pragma unroll
            for (int ntl = 0; ntl < 4; ntl++)
                #pragma unroll
                for (int e = 0; e < 4; e++) acc[mt][ntl][e] = 0.f;

        #pragma unroll
        for (int ks = 0; ks < 4; ks++) {
            uint32_t ah[2][4], al[2][4];
            const int cb = 8*ks + q;
            #pragma unroll
            for (int mt = 0; mt < 2; mt++) {
                int ra = mt*16 + r0, rb = ra + 8;
                ah[mt][0] = zhi[ra*36 + cb];     ah[mt][1] = zhi[rb*36 + cb];
                ah[mt][2] = zhi[ra*36 + cb + 4]; ah[mt][3] = zhi[rb*36 + cb + 4];
                al[mt][0] = zlo[ra*36 + cb];     al[mt][1] = zlo[rb*36 + cb];
                al[mt][2] = zlo[ra*36 + cb + 4]; al[mt][3] = zlo[rb*36 + cb + 4];
            }
            #pragma unroll
            for (int ntl = 0; ntl < 4; ntl++) {
                int nt = ch*4 + ntl;
                int wb = cb*136 + 8*nt + r0;
                uint32_t bh0 = whi[wb], bh1 = whi[wb + 4*136];
                uint32_t bl0 = wlo[wb], bl1 = wlo[wb + 4*136];
                #pragma unroll
                for (int mt = 0; mt < 2; mt++) {
                    mma_bf16(acc[mt][ntl], ah[mt], bh0, bh1);
                    mma_bf16(acc[mt][ntl], ah[mt], bl0, bl1);
                    mma_bf16(acc[mt][ntl], al[mt], bh0, bh1);
                }
            }
        }

        #pragma unroll
        for (int ntl = 0; ntl < 4; ntl++) {
            int nt = ch*4 + ntl;
            float v00 = acc[0][ntl][0], v02 = acc[0][ntl][2];
            float v10 = acc[1][ntl][0], v12 = acc[1][ntl][2];
            float v01 = acc[0][ntl][1], v03 = acc[0][ntl][3];
            float v11 = acc[1][ntl][1], v13 = acc[1][ntl][3];
            float s0 = v00 + v02 + v10 + v12;
            float s1 = v01 + v03 + v11 + v13;
            float q0 = v00*v00 + v02*v02 + v10*v10 + v12*v12;
            float q1 = v01*v01 + v03*v03 + v11*v11 + v13*v13;
            float m0 = fmaxf(fmaxf(v00, v02), fmaxf(v10, v12));
            float m1 = fmaxf(fmaxf(v01, v03), fmaxf(v11, v13));
            #pragma unroll
            for (int off = 4; off < 32; off <<= 1) {
                s0 += __shfl_xor_sync(0xffffffffu, s0, off);
                s1 += __shfl_xor_sync(0xffffffffu, s1, off);
                q0 += __shfl_xor_sync(0xffffffffu, q0, off);
                q1 += __shfl_xor_sync(0xffffffffu, q1, off);
                m0 = fmaxf(m0, __shfl_xor_sync(0xffffffffu, m0, off));
                m1 = fmaxf(m1, __shfl_xor_sync(0xffffffffu, m1, off));
            }
            if (r0 == 0) {   // lanes 0..3
                int c = 8*nt + 2*q;
                atomicAdd(&ssum2[c],   s0); atomicAdd(&ssum2[c+1], s1);
                atomicAdd(&ssq2[c],    q0); atomicAdd(&ssq2[c+1],  q1);
                g_max3[(size_t)g*C3 + c]     = m0;
                g_max3[(size_t)g*C3 + c + 1] = m1;
            }
        }
    }
    __syncthreads();
    atomicAdd(&g_sum2[tid], ssum2[tid]);
    atomicAdd(&g_sq2[tid],  ssq2[tid]);
}

// ---------------- finalize: bn2 + relu on pooled maxes ----------------------
__global__ void finalize_kernel(const float* __restrict__ g2,
                                const float* __restrict__ be2,
                                float* __restrict__ out) {
    __shared__ float sc[C3], sh[C3];
    const int tid = threadIdx.x;
    if (tid < C3) {
        const float inv = 1.0f / (float)CNT;
        float m = g_sum2[tid] * inv;
        float v = g_sq2[tid] * inv - m*m;
        float s = g2[tid] * rsqrtf(v + 0.001f);
        sc[tid] = s; sh[tid] = be2[tid] - m*s;
    }
    __syncthreads();
    for (int i = blockIdx.x * blockDim.x + tid; i < B*P*C3; i += gridDim.x * blockDim.x) {
        int o = i & 127;
        out[OFF_NEWPTS + i] = fmaxf(fmaf(g_max3[i], sc[o], sh[o]), 0.f);
    }
}

// ---------------- launch -----------------------------------------------------
extern "C" void kernel_launch(void* const* d_in, const int* in_sizes, int n_in,
                              void* d_out, int out_size) {
    const float* xyz = (const float*)d_in[0];
    const float* pts = (const float*)d_in[1];
    const float* W0  = (const float*)d_in[2];
    const float* g0  = (const float*)d_in[4];
    const float* be0 = (const float*)d_in[5];
    const float* W1  = (const float*)d_in[6];
    const float* g1  = (const float*)d_in[8];
    const float* be1 = (const float*)d_in[9];
    const float* W2  = (const float*)d_in[10];
    const float* g2  = (const float*)d_in[12];
    const float* be2 = (const float*)d_in[13];
    float* out = (float*)d_out;

    const int smemPts = 3 * N * (int)sizeof(float);   // 49152
    cudaFuncSetAttribute(fps_kernel,   cudaFuncAttributeMaxDynamicSharedMemorySize, smemPts);
    cudaFuncSetAttribute(ballq_kernel, cudaFuncAttributeMaxDynamicSharedMemorySize, smemPts);
    cudaFuncSetAttribute(conv1_mma, cudaFuncAttributeMaxDynamicSharedMemorySize, CV1_SMEM);
    cudaFuncSetAttribute(conv2_mma, cudaFuncAttributeMaxDynamicSharedMemorySize, CV2_SMEM);
    cudaFuncSetAttribute(conv3_mma, cudaFuncAttributeMaxDynamicSharedMemorySize, CV3_SMEM);

    fps_kernel<<<B, FPS_T, smemPts>>>(xyz, out);
    ballq_kernel<<<dim3(P/8, B), 256, smemPts>>>(xyz, out);
    conv1_mma<<<(B*P)/4, 128, CV1_SMEM>>>(xyz, pts, W0);
    conv2_mma<<<(B*P)/4, 128, CV2_SMEM>>>(W1, g0, be0);
    conv3_mma<<<(B*P)/4, 128, CV3_SMEM>>>(W2, g1, be1);
    finalize_kernel<<<2048, 256>>>(g2, be2, out);
}

// round 7
// speedup vs baseline: 1.1954x; 1.1954x over previous
#include <cuda_runtime.h>
#include <cuda_bf16.h>
#include <cstdint>

#define B 16
#define N 4096
#define C 64
#define P 1024      // NPOINT
#define S 32        // NSAMPLE
#define CIN0 67
#define C1 64
#define C2 64
#define C3 128
#define CNT (B*P*S) // 524288 samples per channel for BN

#define OFF_NEWXYZ 0
#define OFF_NEWPTS (B*P*3)                 // 49152
#define OFF_IDX    (B*P*3 + B*P*C3)        // 2146304

typedef unsigned long long ull;

// ---------------- mma.sync bf16 (baseline sm_80+ PTX, works on sm_103) -------
__device__ __forceinline__ void mma_bf16(float* d, const uint32_t* a, uint32_t b0, uint32_t b1) {
    asm volatile("mma.sync.aligned.m16n8k16.row.col.f32.bf16.bf16.f32 "
        "{%0,%1,%2,%3}, {%4,%5,%6,%7}, {%8,%9}, {%0,%1,%2,%3};"
        : "+f"(d[0]), "+f"(d[1]), "+f"(d[2]), "+f"(d[3])
        : "r"(a[0]), "r"(a[1]), "r"(a[2]), "r"(a[3]), "r"(b0), "r"(b1));
}

// split fp32 pair into bf16x2 (hi) and bf16x2 (residual lo); first arg = low half
__device__ __forceinline__ void split2(float a, float b, uint32_t& hi, uint32_t& lo) {
    __nv_bfloat16 ha = __float2bfloat16_rn(a);
    __nv_bfloat16 hb = __float2bfloat16_rn(b);
    __nv_bfloat162 hh = __halves2bfloat162(ha, hb);
    hi = *reinterpret_cast<uint32_t*>(&hh);
    float la = a - __bfloat162float(ha);
    float lb = b - __bfloat162float(hb);
    __nv_bfloat162 ll = __floats2bfloat162_rn(la, lb);
    lo = *reinterpret_cast<uint32_t*>(&ll);
}

// ---------------- scratch (static device memory; no allocations) ------------
__device__ float g_new_xyz[B*P*3];
__device__ int   g_idx[B*P*S];
// y layout: 16B chunks: [group][chunk 0..15][lane 0..31], chunk = 4 channels
__device__ float g_y1[(size_t)B*P*S*C1];   // 134 MB
__device__ float g_y2[(size_t)B*P*S*C2];   // 134 MB
__device__ float g_max3[(size_t)B*P*C3];   // 8 MB

__device__ float g_sum0[C1], g_sq0[C1];
__device__ float g_sum1[C2], g_sq1[C2];
__device__ float g_sum2[C3], g_sq2[C3];

// ---------------- FPS: one block per batch (also zeroes stats) --------------
// (R5-proven version: 256 threads, scalar math, REDUX warp reduce)
#define FPS_T 256
#define FPS_PP (N/FPS_T)   // 16 points per thread
__global__ void fps_kernel(const float* __restrict__ xyz, float* __restrict__ out) {
    extern __shared__ float sm[];
    float* sx = sm; float* sy = sm + N; float* sz = sm + 2*N;
    __shared__ ull skey[2][FPS_T/32];

    const int b = blockIdx.x;
    const int t = threadIdx.x;
    const int lane = t & 31, w = t >> 5;

    if (b == 0) {
        if (t < C1) { g_sum0[t]=0.f; g_sq0[t]=0.f; g_sum1[t]=0.f; g_sq1[t]=0.f; }
        if (t < C3) { g_sum2[t]=0.f; g_sq2[t]=0.f; }
    }

    const float* base = xyz + (size_t)b * N * 3;
    for (int i = t; i < N; i += FPS_T) {
        sx[i] = base[i*3+0]; sy[i] = base[i*3+1]; sz[i] = base[i*3+2];
    }
    __syncthreads();

    float px[FPS_PP], py[FPS_PP], pz[FPS_PP], dd[FPS_PP];
    #pragma unroll
    for (int j = 0; j < FPS_PP; j++) {
        int i = t + j*FPS_T;
        px[j]=sx[i]; py[j]=sy[i]; pz[j]=sz[i]; dd[j]=1e10f;
    }

    int far = 0;
    for (int k = 0; k < P; k++) {
        float fx = sx[far], fy = sy[far], fz = sz[far];
        if (t == 0) {
            size_t gk = (size_t)b*P + k;
            g_new_xyz[gk*3+0]=fx; g_new_xyz[gk*3+1]=fy; g_new_xyz[gk*3+2]=fz;
            out[OFF_NEWXYZ + gk*3+0]=fx; out[OFF_NEWXYZ + gk*3+1]=fy; out[OFF_NEWXYZ + gk*3+2]=fz;
        }
        float bv = -1.f; int bi = 0x7fffffff;
        #pragma unroll
        for (int j = 0; j < FPS_PP; j++) {
            float dx = __fsub_rn(px[j], fx);
            float dy = __fsub_rn(py[j], fy);
            float dz = __fsub_rn(pz[j], fz);
            float d  = __fadd_rn(__fadd_rn(__fmul_rn(dx,dx), __fmul_rn(dy,dy)), __fmul_rn(dz,dz));
            dd[j] = fminf(dd[j], d);
            if (dd[j] > bv) { bv = dd[j]; bi = t + j*FPS_T; }
        }
        unsigned bvb = __float_as_uint(bv);
        unsigned mb  = __reduce_max_sync(0xffffffffu, bvb);
        unsigned bim = (bvb == mb) ? (unsigned)bi : 0x7fffffffu;
        unsigned bmin = __reduce_min_sync(0xffffffffu, bim);
        if (lane == 0) skey[k & 1][w] = ((ull)mb << 32) | (unsigned)(~bmin);
        __syncthreads();
        ull kb = skey[k & 1][0];
        #pragma unroll
        for (int q = 1; q < FPS_T/32; q++) {
            ull o = skey[k & 1][q];
            if (o > kb) kb = o;
        }
        far = (int)(~(unsigned)kb);
    }
}

// ---------------- Ball query: one warp per center ---------------------------
__global__ void ballq_kernel(const float* __restrict__ xyz, float* __restrict__ out) {
    extern __shared__ float sm[];
    float* sx = sm; float* sy = sm + N; float* sz = sm + 2*N;
    const int b = blockIdx.y;
    const int tid = threadIdx.x;
    const float* base = xyz + (size_t)b * N * 3;
    for (int i = tid; i < N; i += blockDim.x) {
        sx[i] = base[i*3+0]; sy[i] = base[i*3+1]; sz[i] = base[i*3+2];
    }
    __syncthreads();

    const int w = tid >> 5, lane = tid & 31;
    const int p = blockIdx.x * 8 + w;
    const int g = b * P + p;
    const float cx = g_new_xyz[g*3+0], cy = g_new_xyz[g*3+1], cz = g_new_xyz[g*3+2];
    const float R2 = (float)(0.4 * 0.4);

    int cnt = 0, first = -1;
    for (int basei = 0; basei < N; basei += 32) {
        int i = basei + lane;
        float dx = __fsub_rn(cx, sx[i]);
        float dy = __fsub_rn(cy, sy[i]);
        float dz = __fsub_rn(cz, sz[i]);
        float d2 = __fadd_rn(__fadd_rn(__fmul_rn(dx,dx), __fmul_rn(dy,dy)), __fmul_rn(dz,dz));
        bool pred = d2 < R2;
        unsigned m = __ballot_sync(0xffffffffu, pred);
        if (first < 0 && m) first = basei + __ffs(m) - 1;
        int rank = cnt + __popc(m & ((1u << lane) - 1u));
        if (pred && rank < S) {
            g_idx[g*S + rank] = i;
            out[OFF_IDX + g*S + rank] = (float)i;
        }
        cnt += __popc(m);
        if (cnt >= S) break;
    }
    int cntc = cnt < S ? cnt : S;
    if (lane >= cntc) {
        g_idx[g*S + lane] = first;
        out[OFF_IDX + g*S + lane] = (float)first;
    }
}

// =============================================================================
// Convs: 2 groups per 128-thread block, 2 warps per group (h = warp&1 handles
// n-tiles [4h,4h+4)). acc = 32 regs/thread -> higher occupancy.
// =============================================================================

// ---------------- conv1: gather + (67->64), K padded to 80 (5 k-steps) ------
// smem: whi @0 (11520), wlo @11520 (11520), zbuf @23040 (2 x 11264),
//       params @45568 (ssum64, ssq64) -> 46080
#define CV1_WLO  11520
#define CV1_ZB   23040
#define CV1_PAR  45568
#define CV1_SMEM 46080

__global__ __launch_bounds__(128) void conv1_mma(const float* __restrict__ xyz,
                                                 const float* __restrict__ pts,
                                                 const float* __restrict__ W0) {
    extern __shared__ char smraw[];
    uint32_t* whi = (uint32_t*)(smraw);
    uint32_t* wlo = (uint32_t*)(smraw + CV1_WLO);
    float* ssum = (float*)(smraw + CV1_PAR);
    float* ssq  = ssum + 64;

    const int tid = threadIdx.x, wid = tid >> 5, lane = tid & 31;
    const int q = lane & 3, r0 = lane >> 2;
    const int gl = wid >> 1, h = wid & 1;
    const int g = blockIdx.x * 2 + gl;
    const int b = g >> 10;

    // W pairs (zero-padded past row 66), row stride 72 words
    for (int idx = tid; idx < 40*64; idx += 128) {
        int kk = idx >> 6, n = idx & 63;
        float a  = (2*kk     < CIN0) ? W0[(2*kk)*C1 + n]   : 0.f;
        float bq = (2*kk + 1 < CIN0) ? W0[(2*kk+1)*C1 + n] : 0.f;
        uint32_t hi, lo;
        split2(a, bq, hi, lo);
        whi[kk*72 + n] = hi; wlo[kk*72 + n] = lo;
    }
    if (tid < 64) { ssum[tid] = 0.f; ssq[tid] = 0.f; }

    uint32_t* zhi = (uint32_t*)(smraw + CV1_ZB) + gl*2816;   // [32][44] words
    uint32_t* zlo = zhi + 1408;

    {   // stage A: lane = sample; warp pair splits the k range (carry chain)
        const int j = g_idx[g*S + lane];
        const float4* pr = (const float4*)(pts + ((size_t)b*N + j)*C);
        uint32_t hi, lo;
        if (h == 0) {
            const float* xr = xyz + ((size_t)b*N + j)*3;
            float rx = xr[0] - g_new_xyz[g*3+0];
            float ry = xr[1] - g_new_xyz[g*3+1];
            float rz = xr[2] - g_new_xyz[g*3+2];
            split2(rx, ry, hi, lo);
            zhi[lane*44 + 0] = hi; zlo[lane*44 + 0] = lo;
            float carry = rz;
            #pragma unroll
            for (int qq = 0; qq < 8; qq++) {
                float4 v = __ldg(pr + qq);
                split2(carry, v.x, hi, lo);
                zhi[lane*44 + 2*qq + 1] = hi; zlo[lane*44 + 2*qq + 1] = lo;
                split2(v.y, v.z, hi, lo);
                zhi[lane*44 + 2*qq + 2] = hi; zlo[lane*44 + 2*qq + 2] = lo;
                carry = v.w;
            }
        } else {
            float carry = __ldg(pr + 7).w;
            #pragma unroll
            for (int qq = 8; qq < 16; qq++) {
                float4 v = __ldg(pr + qq);
                split2(carry, v.x, hi, lo);
                zhi[lane*44 + 2*qq + 1] = hi; zlo[lane*44 + 2*qq + 1] = lo;
                split2(v.y, v.z, hi, lo);
                zhi[lane*44 + 2*qq + 2] = hi; zlo[lane*44 + 2*qq + 2] = lo;
                carry = v.w;
            }
            split2(carry, 0.f, hi, lo);
            zhi[lane*44 + 33] = hi; zlo[lane*44 + 33] = lo;
            #pragma unroll
            for (int kz = 34; kz < 40; kz++) { zhi[lane*44 + kz] = 0u; zlo[lane*44 + kz] = 0u; }
        }
    }
    __syncthreads();

    float acc[2][4][4];
    #pragma unroll
    for (int mt = 0; mt < 2; mt++)
        #pragma unroll
        for (int ntl = 0; ntl < 4; ntl++)
            #pragma unroll
            for (int e = 0; e < 4; e++) acc[mt][ntl][e] = 0.f;

    #pragma unroll
    for (int ks = 0; ks < 5; ks++) {
        uint32_t ah[2][4], al[2][4];
        const int cb = 8*ks + q;
        #pragma unroll
        for (int mt = 0; mt < 2; mt++) {
            int ra = mt*16 + r0, rb = ra + 8;
            ah[mt][0] = zhi[ra*44 + cb];     ah[mt][1] = zhi[rb*44 + cb];
            ah[mt][2] = zhi[ra*44 + cb + 4]; ah[mt][3] = zhi[rb*44 + cb + 4];
            al[mt][0] = zlo[ra*44 + cb];     al[mt][1] = zlo[rb*44 + cb];
            al[mt][2] = zlo[ra*44 + cb + 4]; al[mt][3] = zlo[rb*44 + cb + 4];
        }
        #pragma unroll
        for (int ntl = 0; ntl < 4; ntl++) {
            int nt = 4*h + ntl;
            int wb  = cb*72 + 8*nt + r0;
            uint32_t bh0 = whi[wb], bh1 = whi[wb + 4*72];
            uint32_t bl0 = wlo[wb], bl1 = wlo[wb + 4*72];
            #pragma unroll
            for (int mt = 0; mt < 2; mt++) {
                mma_bf16(acc[mt][ntl], ah[mt], bh0, bh1);
                mma_bf16(acc[mt][ntl], ah[mt], bl0, bl1);
                mma_bf16(acc[mt][ntl], al[mt], bh0, bh1);
            }
        }
    }
    __syncthreads();   // both warps done reading zbuf before overlay

    // D -> smem overlay (stride 68); warp h writes cols [32h, 32h+32)
    float* Ds = (float*)zhi;
    #pragma unroll
    for (int mt = 0; mt < 2; mt++) {
        int ra = mt*16 + r0;
        #pragma unroll
        for (int ntl = 0; ntl < 4; ntl++) {
            int cbb = 8*(4*h + ntl) + 2*q;
            *(float2*)(Ds + ra*68 + cbb)     = make_float2(acc[mt][ntl][0], acc[mt][ntl][1]);
            *(float2*)(Ds + (ra+8)*68 + cbb) = make_float2(acc[mt][ntl][2], acc[mt][ntl][3]);
        }
    }
    __syncwarp();   // warp reads only its own cols below

    // y1 store: warp h handles chunks [8h, 8h+8)
    float4* ydst = (float4*)g_y1 + (size_t)g*512 + lane;
    #pragma unroll
    for (int qq = 8*h; qq < 8*h + 8; qq++)
        ydst[qq*32] = *(float4*)(Ds + lane*68 + 4*qq);

    // column stats: channel c = 32h + lane
    {
        int c = 32*h + lane;
        float s = 0.f, sq = 0.f;
        #pragma unroll 8
        for (int ss = 0; ss < 32; ss++) {
            float x = Ds[ss*68 + c];
            s += x; sq += x*x;
        }
        atomicAdd(&ssum[c], s);
        atomicAdd(&ssq[c],  sq);
    }
    __syncthreads();
    if (tid < 64) {
        atomicAdd(&g_sum0[tid], ssum[tid]);
        atomicAdd(&g_sq0[tid],  ssq[tid]);
    }
}

// ---------------- conv2: bn0+relu, [32x64]@[64x64] --------------------------
// smem: whi @0 (9216), wlo @9216 (9216), zbuf @18432 (2 x 9216),
//       params @36864 (ssc,ssh,ssum,ssq x64) -> 37888
#define CV2_WLO   9216
#define CV2_ZB   18432
#define CV2_PAR  36864
#define CV2_SMEM 37888

__global__ __launch_bounds__(128) void conv2_mma(const float* __restrict__ W1,
                                                 const float* __restrict__ g0p,
                                                 const float* __restrict__ be0) {
    extern __shared__ char smraw[];
    uint32_t* whi = (uint32_t*)(smraw);
    uint32_t* wlo = (uint32_t*)(smraw + CV2_WLO);
    float* ssc  = (float*)(smraw + CV2_PAR);
    float* ssh  = ssc + 64;
    float* ssum = ssh + 64;
    float* ssq  = ssum + 64;

    const int tid = threadIdx.x, wid = tid >> 5, lane = tid & 31;
    const int q = lane & 3, r0 = lane >> 2;
    const int gl = wid >> 1, h = wid & 1;
    const int g = blockIdx.x * 2 + gl;

    for (int idx = tid; idx < 32*64; idx += 128) {
        int kk = idx >> 6, n = idx & 63;
        uint32_t hi, lo;
        split2(W1[(2*kk)*C2 + n], W1[(2*kk+1)*C2 + n], hi, lo);
        whi[kk*72 + n] = hi; wlo[kk*72 + n] = lo;
    }
    if (tid < 64) {
        const float inv = 1.0f / (float)CNT;
        float m = g_sum0[tid] * inv;
        float v = g_sq0[tid] * inv - m*m;
        float sc = g0p[tid] * rsqrtf(v + 0.001f);
        ssc[tid] = sc; ssh[tid] = be0[tid] - m*sc;
        ssum[tid] = 0.f; ssq[tid] = 0.f;
    }
    __syncthreads();   // BN params must be visible before staging uses them

    uint32_t* zhi = (uint32_t*)(smraw + CV2_ZB) + gl*2304;   // [32][36] words
    uint32_t* zlo = zhi + 1152;

    {   // stage A: warp h stages chunks [8h, 8h+8)
        const float4* xsrc = (const float4*)g_y1 + (size_t)g*512 + lane;
        #pragma unroll
        for (int qq = 8*h; qq < 8*h + 8; qq++) {
            float4 v = xsrc[qq*32];
            int c = qq*4;
            float z0 = fmaxf(fmaf(v.x, ssc[c+0], ssh[c+0]), 0.f);
            float z1 = fmaxf(fmaf(v.y, ssc[c+1], ssh[c+1]), 0.f);
            float z2 = fmaxf(fmaf(v.z, ssc[c+2], ssh[c+2]), 0.f);
            float z3 = fmaxf(fmaf(v.w, ssc[c+3], ssh[c+3]), 0.f);
            uint32_t h0, l0, h1, l1;
            split2(z0, z1, h0, l0); split2(z2, z3, h1, l1);
            zhi[lane*36 + 2*qq]     = h0; zhi[lane*36 + 2*qq + 1] = h1;
            zlo[lane*36 + 2*qq]     = l0; zlo[lane*36 + 2*qq + 1] = l1;
        }
    }
    __syncthreads();

    float acc[2][4][4];
    #pragma unroll
    for (int mt = 0; mt < 2; mt++)
        #pragma unroll
        for (int ntl = 0; ntl < 4; ntl++)
            #pragma unroll
            for (int e = 0; e < 4; e++) acc[mt][ntl][e] = 0.f;

    #pragma unroll
    for (int ks = 0; ks < 4; ks++) {
        uint32_t ah[2][4], al[2][4];
        const int cb = 8*ks + q;
        #pragma unroll
        for (int mt = 0; mt < 2; mt++) {
            int ra = mt*16 + r0, rb = ra + 8;
            ah[mt][0] = zhi[ra*36 + cb];     ah[mt][1] = zhi[rb*36 + cb];
            ah[mt][2] = zhi[ra*36 + cb + 4]; ah[mt][3] = zhi[rb*36 + cb + 4];
            al[mt][0] = zlo[ra*36 + cb];     al[mt][1] = zlo[rb*36 + cb];
            al[mt][2] = zlo[ra*36 + cb + 4]; al[mt][3] = zlo[rb*36 + cb + 4];
        }
        #pragma unroll
        for (int ntl = 0; ntl < 4; ntl++) {
            int nt = 4*h + ntl;
            int wb  = cb*72 + 8*nt + r0;
            uint32_t bh0 = whi[wb], bh1 = whi[wb + 4*72];
            uint32_t bl0 = wlo[wb], bl1 = wlo[wb + 4*72];
            #pragma unroll
            for (int mt = 0; mt < 2; mt++) {
                mma_bf16(acc[mt][ntl], ah[mt], bh0, bh1);
                mma_bf16(acc[mt][ntl], ah[mt], bl0, bl1);
                mma_bf16(acc[mt][ntl], al[mt], bh0, bh1);
            }
        }
    }
    __syncthreads();

    float* Ds = (float*)zhi;
    #pragma unroll
    for (int mt = 0; mt < 2; mt++) {
        int ra = mt*16 + r0;
        #pragma unroll
        for (int ntl = 0; ntl < 4; ntl++) {
            int cbb = 8*(4*h + ntl) + 2*q;
            *(float2*)(Ds + ra*68 + cbb)     = make_float2(acc[mt][ntl][0], acc[mt][ntl][1]);
            *(float2*)(Ds + (ra+8)*68 + cbb) = make_float2(acc[mt][ntl][2], acc[mt][ntl][3]);
        }
    }
    __syncwarp();

    float4* ydst = (float4*)g_y2 + (size_t)g*512 + lane;
    #pragma unroll
    for (int qq = 8*h; qq < 8*h + 8; qq++)
        ydst[qq*32] = *(float4*)(Ds + lane*68 + 4*qq);

    {
        int c = 32*h + lane;
        float s = 0.f, sq = 0.f;
        #pragma unroll 8
        for (int ss = 0; ss < 32; ss++) {
            float x = Ds[ss*68 + c];
            s += x; sq += x*x;
        }
        atomicAdd(&ssum[c], s);
        atomicAdd(&ssq[c],  sq);
    }
    __syncthreads();
    if (tid < 64) {
        atomicAdd(&g_sum1[tid], ssum[tid]);
        atomicAdd(&g_sq1[tid],  ssq[tid]);
    }
}

// ---------------- conv3: bn1+relu, [32x64]@[64x128] + stats + max -----------
// smem: whi @0 (17408), wlo @17408 (17408), zbuf @34816 (2 x 9216),
//       params @53248 (ssc64, ssh64, ssum128, ssq128) -> 54784
#define CV3_WLO  17408
#define CV3_ZB   34816
#define CV3_PAR  53248
#define CV3_SMEM 54784

__global__ __launch_bounds__(128) void conv3_mma(const float* __restrict__ W2,
                                                 const float* __restrict__ g1p,
                                                 const float* __restrict__ be1) {
    extern __shared__ char smraw[];
    uint32_t* whi = (uint32_t*)(smraw);
    uint32_t* wlo = (uint32_t*)(smraw + CV3_WLO);
    float* ssc   = (float*)(smraw + CV3_PAR);
    float* ssh   = ssc + 64;
    float* ssum2 = ssh + 64;    // [128]
    float* ssq2  = ssum2 + 128; // [128]

    const int tid = threadIdx.x, wid = tid >> 5, lane = tid & 31;
    const int q = lane & 3, r0 = lane >> 2;
    const int gl = wid >> 1, h = wid & 1;
    const int g = blockIdx.x * 2 + gl;

    for (int idx = tid; idx < 32*128; idx += 128) {
        int kk = idx >> 7, n = idx & 127;
        uint32_t hi, lo;
        split2(W2[(2*kk)*C3 + n], W2[(2*kk+1)*C3 + n], hi, lo);
        whi[kk*136 + n] = hi; wlo[kk*136 + n] = lo;
    }
    if (tid < 64) {
        const float inv = 1.0f / (float)CNT;
        float m = g_sum1[tid] * inv;
        float v = g_sq1[tid] * inv - m*m;
        float sc = g1p[tid] * rsqrtf(v + 0.001f);
        ssc[tid] = sc; ssh[tid] = be1[tid] - m*sc;
    }
    ssum2[tid] = 0.f; ssq2[tid] = 0.f;
    __syncthreads();

    uint32_t* zhi = (uint32_t*)(smraw + CV3_ZB) + gl*2304;
    uint32_t* zlo = zhi + 1152;

    {   // stage A: warp h stages chunks [8h, 8h+8)
        const float4* xsrc = (const float4*)g_y2 + (size_t)g*512 + lane;
        #pragma unroll
        for (int qq = 8*h; qq < 8*h + 8; qq++) {
            float4 v = xsrc[qq*32];
            int c = qq*4;
            float z0 = fmaxf(fmaf(v.x, ssc[c+0], ssh[c+0]), 0.f);
            float z1 = fmaxf(fmaf(v.y, ssc[c+1], ssh[c+1]), 0.f);
            float z2 = fmaxf(fmaf(v.z, ssc[c+2], ssh[c+2]), 0.f);
            float z3 = fmaxf(fmaf(v.w, ssc[c+3], ssh[c+3]), 0.f);
            uint32_t h0, l0, h1, l1;
            split2(z0, z1, h0, l0); split2(z2, z3, h1, l1);
            zhi[lane*36 + 2*qq]     = h0; zhi[lane*36 + 2*qq + 1] = h1;
            zlo[lane*36 + 2*qq]     = l0; zlo[lane*36 + 2*qq + 1] = l1;
        }
    }
    __syncthreads();

    // warp h handles ch-chunks {2h, 2h+1} (32 cols each)
    #pragma unroll 1
    for (int chl = 0; chl < 2; chl++) {
        int ch = 2*h + chl;
        float acc[2][4][4];
        #pragma unroll
        for (int mt = 0; mt < 2; mt++)
            #pragma unroll
            for (int ntl = 0; ntl < 4; ntl++)
                #pragma unroll
                for (int e = 0; e < 4; e++) acc[mt][ntl][e] = 0.f;

        #pragma unroll
        for (int ks = 0; ks < 4; ks++) {
            uint32_t ah[2][4], al[2][4];
            const int cb = 8*ks + q;
            #pragma unroll
            for (int mt = 0; mt < 2; mt++) {
                int ra = mt*16 + r0, rb = ra + 8;
                ah[mt][0] = zhi[ra*36 + cb];     ah[mt][1] = zhi[rb*36 + cb];
                ah[mt][2] = zhi[ra*36 + cb + 4]; ah[mt][3] = zhi[rb*36 + cb + 4];
                al[mt][0] = zlo[ra*36 + cb];     al[mt][1] = zlo[rb*36 + cb];
                al[mt][2] = zlo[ra*36 + cb + 4]; al[mt][3] = zlo[rb*36 + cb + 4];
            }
            #pragma unroll
            for (int ntl = 0; ntl < 4; ntl++) {
                int nt = ch*4 + ntl;
                int wb = cb*136 + 8*nt + r0;
                uint32_t bh0 = whi[wb], bh1 = whi[wb + 4*136];
                uint32_t bl0 = wlo[wb], bl1 = wlo[wb + 4*136];
                #pragma unroll
                for (int mt = 0; mt < 2; mt++) {
                    mma_bf16(acc[mt][ntl], ah[mt], bh0, bh1);
                    mma_bf16(acc[mt][ntl], ah[mt], bl0, bl1);
                    mma_bf16(acc[mt][ntl], al[mt], bh0, bh1);
                }
            }
        }

        #pragma unroll
        for (int ntl = 0; ntl < 4; ntl++) {
            int nt = ch*4 + ntl;
            float v00 = acc[0][ntl][0], v02 = acc[0][ntl][2];
            float v10 = acc[1][ntl][0], v12 = acc[1][ntl][2];
            float v01 = acc[0][ntl][1], v03 = acc[0][ntl][3];
            float v11 = acc[1][ntl][1], v13 = acc[1][ntl][3];
            float s0 = v00 + v02 + v10 + v12;
            float s1 = v01 + v03 + v11 + v13;
            float q0 = v00*v00 + v02*v02 + v10*v10 + v12*v12;
            float q1 = v01*v01 + v03*v03 + v11*v11 + v13*v13;
            float m0 = fmaxf(fmaxf(v00, v02), fmaxf(v10, v12));
            float m1 = fmaxf(fmaxf(v01, v03), fmaxf(v11, v13));
            #pragma unroll
            for (int off = 4; off < 32; off <<= 1) {
                s0 += __shfl_xor_sync(0xffffffffu, s0, off);
                s1 += __shfl_xor_sync(0xffffffffu, s1, off);
                q0 += __shfl_xor_sync(0xffffffffu, q0, off);
                q1 += __shfl_xor_sync(0xffffffffu, q1, off);
                m0 = fmaxf(m0, __shfl_xor_sync(0xffffffffu, m0, off));
                m1 = fmaxf(m1, __shfl_xor_sync(0xffffffffu, m1, off));
            }
            if (r0 == 0) {   // lanes 0..3
                int c = 8*nt + 2*q;
                atomicAdd(&ssum2[c],   s0); atomicAdd(&ssum2[c+1], s1);
                atomicAdd(&ssq2[c],    q0); atomicAdd(&ssq2[c+1],  q1);
                g_max3[(size_t)g*C3 + c]     = m0;
                g_max3[(size_t)g*C3 + c + 1] = m1;
            }
        }
    }
    __syncthreads();
    atomicAdd(&g_sum2[tid], ssum2[tid]);
    atomicAdd(&g_sq2[tid],  ssq2[tid]);
}

// ---------------- finalize: bn2 + relu on pooled maxes ----------------------
__global__ void finalize_kernel(const float* __restrict__ g2,
                                const float* __restrict__ be2,
                                float* __restrict__ out) {
    __shared__ float sc[C3], sh[C3];
    const int tid = threadIdx.x;
    if (tid < C3) {
        const float inv = 1.0f / (float)CNT;
        float m = g_sum2[tid] * inv;
        float v = g_sq2[tid] * inv - m*m;
        float s = g2[tid] * rsqrtf(v + 0.001f);
        sc[tid] = s; sh[tid] = be2[tid] - m*s;
    }
    __syncthreads();
    for (int i = blockIdx.x * blockDim.x + tid; i < B*P*C3; i += gridDim.x * blockDim.x) {
        int o = i & 127;
        out[OFF_NEWPTS + i] = fmaxf(fmaf(g_max3[i], sc[o], sh[o]), 0.f);
    }
}

// ---------------- launch -----------------------------------------------------
extern "C" void kernel_launch(void* const* d_in, const int* in_sizes, int n_in,
                              void* d_out, int out_size) {
    const float* xyz = (const float*)d_in[0];
    const float* pts = (const float*)d_in[1];
    const float* W0  = (const float*)d_in[2];
    const float* g0  = (const float*)d_in[4];
    const float* be0 = (const float*)d_in[5];
    const float* W1  = (const float*)d_in[6];
    const float* g1  = (const float*)d_in[8];
    const float* be1 = (const float*)d_in[9];
    const float* W2  = (const float*)d_in[10];
    const float* g2  = (const float*)d_in[12];
    const float* be2 = (const float*)d_in[13];
    float* out = (float*)d_out;

    const int smemPts = 3 * N * (int)sizeof(float);   // 49152
    cudaFuncSetAttribute(fps_kernel,   cudaFuncAttributeMaxDynamicSharedMemorySize, smemPts);
    cudaFuncSetAttribute(ballq_kernel, cudaFuncAttributeMaxDynamicSharedMemorySize, smemPts);
    cudaFuncSetAttribute(conv1_mma, cudaFuncAttributeMaxDynamicSharedMemorySize, CV1_SMEM);
    cudaFuncSetAttribute(conv2_mma, cudaFuncAttributeMaxDynamicSharedMemorySize, CV2_SMEM);
    cudaFuncSetAttribute(conv3_mma, cudaFuncAttributeMaxDynamicSharedMemorySize, CV3_SMEM);

    fps_kernel<<<B, FPS_T, smemPts>>>(xyz, out);
    ballq_kernel<<<dim3(P/8, B), 256, smemPts>>>(xyz, out);
    conv1_mma<<<(B*P)/2, 128, CV1_SMEM>>>(xyz, pts, W0);
    conv2_mma<<<(B*P)/2, 128, CV2_SMEM>>>(W1, g0, be0);
    conv3_mma<<<(B*P)/2, 128, CV3_SMEM>>>(W2, g1, be1);
    finalize_kernel<<<2048, 256>>>(g2, be2, out);
}

// round 8
// speedup vs baseline: 1.2125x; 1.0143x over previous
#include <cuda_runtime.h>
#include <cuda_bf16.h>
#include <cstdint>

#define B 16
#define N 4096
#define C 64
#define P 1024      // NPOINT
#define S 32        // NSAMPLE
#define CIN0 67
#define C1 64
#define C2 64
#define C3 128
#define CNT (B*P*S) // 524288 samples per channel for BN

#define OFF_NEWXYZ 0
#define OFF_NEWPTS (B*P*3)                 // 49152
#define OFF_IDX    (B*P*3 + B*P*C3)        // 2146304

typedef unsigned long long ull;

// ---------------- mma.sync bf16 (baseline sm_80+ PTX, works on sm_103) -------
__device__ __forceinline__ void mma_bf16(float* d, const uint32_t* a, uint32_t b0, uint32_t b1) {
    asm volatile("mma.sync.aligned.m16n8k16.row.col.f32.bf16.bf16.f32 "
        "{%0,%1,%2,%3}, {%4,%5,%6,%7}, {%8,%9}, {%0,%1,%2,%3};"
        : "+f"(d[0]), "+f"(d[1]), "+f"(d[2]), "+f"(d[3])
        : "r"(a[0]), "r"(a[1]), "r"(a[2]), "r"(a[3]), "r"(b0), "r"(b1));
}

// split fp32 pair into bf16x2 (hi) and bf16x2 (residual lo); first arg = low half
__device__ __forceinline__ void split2(float a, float b, uint32_t& hi, uint32_t& lo) {
    __nv_bfloat16 ha = __float2bfloat16_rn(a);
    __nv_bfloat16 hb = __float2bfloat16_rn(b);
    __nv_bfloat162 hh = __halves2bfloat162(ha, hb);
    hi = *reinterpret_cast<uint32_t*>(&hh);
    float la = a - __bfloat162float(ha);
    float lb = b - __bfloat162float(hb);
    __nv_bfloat162 ll = __floats2bfloat162_rn(la, lb);
    lo = *reinterpret_cast<uint32_t*>(&ll);
}

// ---------------- scratch (static device memory; no allocations) ------------
__device__ float g_new_xyz[B*P*3];
__device__ int   g_idx[B*P*S];
// y layout: 16B chunks: [group][chunk 0..15][lane 0..31], chunk = 4 channels
__device__ float g_y1[(size_t)B*P*S*C1];   // 134 MB
__device__ float g_y2[(size_t)B*P*S*C2];   // 134 MB
__device__ float g_max3[(size_t)B*P*C3];   // 8 MB

__device__ float g_sum0[C1], g_sq0[C1];
__device__ float g_sum1[C2], g_sq1[C2];
__device__ float g_sum2[C3], g_sq2[C3];

// pre-split weight pair tables: .x = bf16x2 hi, .y = bf16x2 lo
__device__ uint2 g_w0p[40*64];
__device__ uint2 g_w1p[32*64];
__device__ uint2 g_w2p[32*128];

// ---------------- setup: split all weights once ------------------------------
__global__ void wsplit_kernel(const float* __restrict__ W0,
                              const float* __restrict__ W1,
                              const float* __restrict__ W2) {
    int i = blockIdx.x * blockDim.x + threadIdx.x;
    if (i < 40*64) {
        int kk = i >> 6, n = i & 63;
        float a  = (2*kk     < CIN0) ? W0[(2*kk)*C1 + n]   : 0.f;
        float bq = (2*kk + 1 < CIN0) ? W0[(2*kk+1)*C1 + n] : 0.f;
        uint32_t hi, lo; split2(a, bq, hi, lo);
        g_w0p[i] = make_uint2(hi, lo);
    }
    if (i < 32*64) {
        int kk = i >> 6, n = i & 63;
        uint32_t hi, lo;
        split2(W1[(2*kk)*C2 + n], W1[(2*kk+1)*C2 + n], hi, lo);
        g_w1p[i] = make_uint2(hi, lo);
    }
    if (i < 32*128) {
        int kk = i >> 7, n = i & 127;
        uint32_t hi, lo;
        split2(W2[(2*kk)*C3 + n], W2[(2*kk+1)*C3 + n], hi, lo);
        g_w2p[i] = make_uint2(hi, lo);
    }
}

// ---------------- FPS: one block per batch (also zeroes stats) --------------
#define FPS_T 256
#define FPS_PP (N/FPS_T)   // 16 points per thread
__global__ void fps_kernel(const float* __restrict__ xyz, float* __restrict__ out) {
    extern __shared__ float sm[];
    float* sx = sm; float* sy = sm + N; float* sz = sm + 2*N;
    __shared__ ull skey[2][FPS_T/32];

    const int b = blockIdx.x;
    const int t = threadIdx.x;
    const int lane = t & 31, w = t >> 5;

    if (b == 0) {
        if (t < C1) { g_sum0[t]=0.f; g_sq0[t]=0.f; g_sum1[t]=0.f; g_sq1[t]=0.f; }
        if (t < C3) { g_sum2[t]=0.f; g_sq2[t]=0.f; }
    }

    const float* base = xyz + (size_t)b * N * 3;
    for (int i = t; i < N; i += FPS_T) {
        sx[i] = base[i*3+0]; sy[i] = base[i*3+1]; sz[i] = base[i*3+2];
    }
    __syncthreads();

    float px[FPS_PP], py[FPS_PP], pz[FPS_PP], dd[FPS_PP];
    #pragma unroll
    for (int j = 0; j < FPS_PP; j++) {
        int i = t + j*FPS_T;
        px[j]=sx[i]; py[j]=sy[i]; pz[j]=sz[i]; dd[j]=1e10f;
    }

    int far = 0;
    for (int k = 0; k < P; k++) {
        float fx = sx[far], fy = sy[far], fz = sz[far];
        if (t == 0) {
            size_t gk = (size_t)b*P + k;
            g_new_xyz[gk*3+0]=fx; g_new_xyz[gk*3+1]=fy; g_new_xyz[gk*3+2]=fz;
            out[OFF_NEWXYZ + gk*3+0]=fx; out[OFF_NEWXYZ + gk*3+1]=fy; out[OFF_NEWXYZ + gk*3+2]=fz;
        }
        float bv = -1.f; int bi = 0x7fffffff;
        #pragma unroll
        for (int j = 0; j < FPS_PP; j++) {
            float dx = __fsub_rn(px[j], fx);
            float dy = __fsub_rn(py[j], fy);
            float dz = __fsub_rn(pz[j], fz);
            float d  = __fadd_rn(__fadd_rn(__fmul_rn(dx,dx), __fmul_rn(dy,dy)), __fmul_rn(dz,dz));
            dd[j] = fminf(dd[j], d);
            if (dd[j] > bv) { bv = dd[j]; bi = t + j*FPS_T; }
        }
        unsigned bvb = __float_as_uint(bv);
        unsigned mb  = __reduce_max_sync(0xffffffffu, bvb);
        unsigned bim = (bvb == mb) ? (unsigned)bi : 0x7fffffffu;
        unsigned bmin = __reduce_min_sync(0xffffffffu, bim);
        if (lane == 0) skey[k & 1][w] = ((ull)mb << 32) | (unsigned)(~bmin);
        __syncthreads();
        ull kb = skey[k & 1][0];
        #pragma unroll
        for (int q = 1; q < FPS_T/32; q++) {
            ull o = skey[k & 1][q];
            if (o > kb) kb = o;
        }
        far = (int)(~(unsigned)kb);
    }
}

// ---------------- Ball query: 64 centers per block, 8 per warp --------------
__global__ void ballq_kernel(const float* __restrict__ xyz, float* __restrict__ out) {
    extern __shared__ float sm[];
    float* sx = sm; float* sy = sm + N; float* sz = sm + 2*N;
    const int b = blockIdx.y;
    const int tid = threadIdx.x;
    const float* base = xyz + (size_t)b * N * 3;
    for (int i = tid; i < N; i += blockDim.x) {
        sx[i] = base[i*3+0]; sy[i] = base[i*3+1]; sz[i] = base[i*3+2];
    }
    __syncthreads();

    const int w = tid >> 5, lane = tid & 31;
    const float R2 = (float)(0.4 * 0.4);

    #pragma unroll 1
    for (int ci = 0; ci < 8; ci++) {
        const int p = blockIdx.x * 64 + w * 8 + ci;
        const int g = b * P + p;
        const float cx = g_new_xyz[g*3+0], cy = g_new_xyz[g*3+1], cz = g_new_xyz[g*3+2];

        int cnt = 0, first = -1;
        for (int basei = 0; basei < N; basei += 32) {
            int i = basei + lane;
            float dx = __fsub_rn(cx, sx[i]);
            float dy = __fsub_rn(cy, sy[i]);
            float dz = __fsub_rn(cz, sz[i]);
            float d2 = __fadd_rn(__fadd_rn(__fmul_rn(dx,dx), __fmul_rn(dy,dy)), __fmul_rn(dz,dz));
            bool pred = d2 < R2;
            unsigned m = __ballot_sync(0xffffffffu, pred);
            if (first < 0 && m) first = basei + __ffs(m) - 1;
            int rank = cnt + __popc(m & ((1u << lane) - 1u));
            if (pred && rank < S) {
                g_idx[g*S + rank] = i;
                out[OFF_IDX + g*S + rank] = (float)i;
            }
            cnt += __popc(m);
            if (cnt >= S) break;
        }
        int cntc = cnt < S ? cnt : S;
        if (lane >= cntc) {
            g_idx[g*S + lane] = first;
            out[OFF_IDX + g*S + lane] = (float)first;
        }
    }
}

// =============================================================================
// Convs: 4 groups per 128-thread block, one warp per group (R5-proven shape),
// weights pre-split (uint2 hi/lo copy into smem).
// =============================================================================

// ---------------- conv1: gather + (67->64), K padded to 80 (5 k-steps) ------
#define CV1_WLO  11520
#define CV1_ZB   23040
#define CV1_PAR  68096
#define CV1_SMEM 68608

__global__ __launch_bounds__(128) void conv1_mma(const float* __restrict__ xyz,
                                                 const float* __restrict__ pts) {
    extern __shared__ char smraw[];
    uint32_t* whi = (uint32_t*)(smraw);
    uint32_t* wlo = (uint32_t*)(smraw + CV1_WLO);
    float* ssum = (float*)(smraw + CV1_PAR);
    float* ssq  = ssum + 64;

    const int tid = threadIdx.x, wid = tid >> 5, lane = tid & 31;
    const int q = lane & 3, r0 = lane >> 2;
    const int g = blockIdx.x * 4 + wid;
    const int b = g >> 10;

    for (int idx = tid; idx < 40*64; idx += 128) {
        uint2 v = g_w0p[idx];
        int kk = idx >> 6, n = idx & 63;
        whi[kk*72 + n] = v.x; wlo[kk*72 + n] = v.y;
    }
    if (tid < 64) { ssum[tid] = 0.f; ssq[tid] = 0.f; }
    __syncthreads();

    uint32_t* zhi = (uint32_t*)(smraw + CV1_ZB) + wid*2816;   // [32][44] words
    uint32_t* zlo = zhi + 1408;

    {   // stage A: lane = sample; gather xyz rel + pts, split, zero-pad
        const int j = g_idx[g*S + lane];
        const float* xr = xyz + ((size_t)b*N + j)*3;
        float rx = xr[0] - g_new_xyz[g*3+0];
        float ry = xr[1] - g_new_xyz[g*3+1];
        float rz = xr[2] - g_new_xyz[g*3+2];
        uint32_t hi, lo;
        split2(rx, ry, hi, lo);
        zhi[lane*44 + 0] = hi; zlo[lane*44 + 0] = lo;

        const float4* pr = (const float4*)(pts + ((size_t)b*N + j)*C);
        float carry = rz;
        int kk = 1;
        #pragma unroll
        for (int qq = 0; qq < 16; qq++) {
            float4 v = __ldg(pr + qq);
            split2(carry, v.x, hi, lo);
            zhi[lane*44 + kk] = hi; zlo[lane*44 + kk] = lo; kk++;
            split2(v.y, v.z, hi, lo);
            zhi[lane*44 + kk] = hi; zlo[lane*44 + kk] = lo; kk++;
            carry = v.w;
        }
        split2(carry, 0.f, hi, lo);
        zhi[lane*44 + 33] = hi; zlo[lane*44 + 33] = lo;
        #pragma unroll
        for (int kz = 34; kz < 40; kz++) { zhi[lane*44 + kz] = 0u; zlo[lane*44 + kz] = 0u; }
    }
    __syncwarp();

    float acc[2][8][4];
    #pragma unroll
    for (int mt = 0; mt < 2; mt++)
        #pragma unroll
        for (int nt = 0; nt < 8; nt++)
            #pragma unroll
            for (int e = 0; e < 4; e++) acc[mt][nt][e] = 0.f;

    #pragma unroll
    for (int ks = 0; ks < 5; ks++) {
        uint32_t ah[2][4], al[2][4];
        const int cb = 8*ks + q;
        #pragma unroll
        for (int mt = 0; mt < 2; mt++) {
            int ra = mt*16 + r0, rb = ra + 8;
            ah[mt][0] = zhi[ra*44 + cb];     ah[mt][1] = zhi[rb*44 + cb];
            ah[mt][2] = zhi[ra*44 + cb + 4]; ah[mt][3] = zhi[rb*44 + cb + 4];
            al[mt][0] = zlo[ra*44 + cb];     al[mt][1] = zlo[rb*44 + cb];
            al[mt][2] = zlo[ra*44 + cb + 4]; al[mt][3] = zlo[rb*44 + cb + 4];
        }
        #pragma unroll
        for (int nt = 0; nt < 8; nt++) {
            int wb  = cb*72 + 8*nt + r0;
            uint32_t bh0 = whi[wb], bh1 = whi[wb + 4*72];
            uint32_t bl0 = wlo[wb], bl1 = wlo[wb + 4*72];
            #pragma unroll
            for (int mt = 0; mt < 2; mt++) {
                mma_bf16(acc[mt][nt], ah[mt], bh0, bh1);
                mma_bf16(acc[mt][nt], ah[mt], bl0, bl1);
                mma_bf16(acc[mt][nt], al[mt], bh0, bh1);
            }
        }
    }
    __syncwarp();

    // D -> smem overlay (stride 68)
    float* Ds = (float*)zhi;
    #pragma unroll
    for (int mt = 0; mt < 2; mt++) {
        int ra = mt*16 + r0;
        #pragma unroll
        for (int nt = 0; nt < 8; nt++) {
            int cbb = 8*nt + 2*q;
            *(float2*)(Ds + ra*68 + cbb)     = make_float2(acc[mt][nt][0], acc[mt][nt][1]);
            *(float2*)(Ds + (ra+8)*68 + cbb) = make_float2(acc[mt][nt][2], acc[mt][nt][3]);
        }
    }
    __syncwarp();

    float4* ydst = (float4*)g_y1 + (size_t)g*512 + lane;
    #pragma unroll
    for (int qq = 0; qq < 16; qq++)
        ydst[qq*32] = *(float4*)(Ds + lane*68 + 4*qq);

    #pragma unroll
    for (int cp = 0; cp < 2; cp++) {
        int c = lane + 32*cp;
        float s = 0.f, sq = 0.f;
        #pragma unroll 8
        for (int ss = 0; ss < 32; ss++) {
            float x = Ds[ss*68 + c];
            s += x; sq += x*x;
        }
        atomicAdd(&ssum[c], s);
        atomicAdd(&ssq[c],  sq);
    }
    __syncthreads();
    if (tid < 64) {
        atomicAdd(&g_sum0[tid], ssum[tid]);
        atomicAdd(&g_sq0[tid],  ssq[tid]);
    }
}

// ---------------- conv2: bn0+relu, [32x64]@[64x64] --------------------------
#define CV2_WLO   9216
#define CV2_ZB   18432
#define CV2_PAR  55296
#define CV2_SMEM 56320

__global__ __launch_bounds__(128) void conv2_mma(const float* __restrict__ g0p,
                                                 const float* __restrict__ be0) {
    extern __shared__ char smraw[];
    uint32_t* whi = (uint32_t*)(smraw);
    uint32_t* wlo = (uint32_t*)(smraw + CV2_WLO);
    float* ssc  = (float*)(smraw + CV2_PAR);
    float* ssh  = ssc + 64;
    float* ssum = ssh + 64;
    float* ssq  = ssum + 64;

    const int tid = threadIdx.x, wid = tid >> 5, lane = tid & 31;
    const int q = lane & 3, r0 = lane >> 2;
    const int g = blockIdx.x * 4 + wid;

    for (int idx = tid; idx < 32*64; idx += 128) {
        uint2 v = g_w1p[idx];
        int kk = idx >> 6, n = idx & 63;
        whi[kk*72 + n] = v.x; wlo[kk*72 + n] = v.y;
    }
    if (tid < 64) {
        const float inv = 1.0f / (float)CNT;
        float m = g_sum0[tid] * inv;
        float v = g_sq0[tid] * inv - m*m;
        float sc = g0p[tid] * rsqrtf(v + 0.001f);
        ssc[tid] = sc; ssh[tid] = be0[tid] - m*sc;
        ssum[tid] = 0.f; ssq[tid] = 0.f;
    }
    __syncthreads();

    uint32_t* zhi = (uint32_t*)(smraw + CV2_ZB) + wid*2304;   // [32][36] words
    uint32_t* zlo = zhi + 1152;

    {   // stage A: lane = sample; BN0 + relu + split
        const float4* xsrc = (const float4*)g_y1 + (size_t)g*512 + lane;
        #pragma unroll
        for (int qq = 0; qq < 16; qq++) {
            float4 v = xsrc[qq*32];
            int c = qq*4;
            float z0 = fmaxf(fmaf(v.x, ssc[c+0], ssh[c+0]), 0.f);
            float z1 = fmaxf(fmaf(v.y, ssc[c+1], ssh[c+1]), 0.f);
            float z2 = fmaxf(fmaf(v.z, ssc[c+2], ssh[c+2]), 0.f);
            float z3 = fmaxf(fmaf(v.w, ssc[c+3], ssh[c+3]), 0.f);
            uint32_t h0, l0, h1, l1;
            split2(z0, z1, h0, l0); split2(z2, z3, h1, l1);
            zhi[lane*36 + 2*qq]     = h0; zhi[lane*36 + 2*qq + 1] = h1;
            zlo[lane*36 + 2*qq]     = l0; zlo[lane*36 + 2*qq + 1] = l1;
        }
    }
    __syncwarp();

    float acc[2][8][4];
    #pragma unroll
    for (int mt = 0; mt < 2; mt++)
        #pragma unroll
        for (int nt = 0; nt < 8; nt++)
            #pragma unroll
            for (int e = 0; e < 4; e++) acc[mt][nt][e] = 0.f;

    #pragma unroll
    for (int ks = 0; ks < 4; ks++) {
        uint32_t ah[2][4], al[2][4];
        const int cb = 8*ks + q;
        #pragma unroll
        for (int mt = 0; mt < 2; mt++) {
            int ra = mt*16 + r0, rb = ra + 8;
            ah[mt][0] = zhi[ra*36 + cb];     ah[mt][1] = zhi[rb*36 + cb];
            ah[mt][2] = zhi[ra*36 + cb + 4]; ah[mt][3] = zhi[rb*36 + cb + 4];
            al[mt][0] = zlo[ra*36 + cb];     al[mt][1] = zlo[rb*36 + cb];
            al[mt][2] = zlo[ra*36 + cb + 4]; al[mt][3] = zlo[rb*36 + cb + 4];
        }
        #pragma unroll
        for (int nt = 0; nt < 8; nt++) {
            int wb  = cb*72 + 8*nt + r0;
            uint32_t bh0 = whi[wb], bh1 = whi[wb + 4*72];
            uint32_t bl0 = wlo[wb], bl1 = wlo[wb + 4*72];
            #pragma unroll
            for (int mt = 0; mt < 2; mt++) {
                mma_bf16(acc[mt][nt], ah[mt], bh0, bh1);
                mma_bf16(acc[mt][nt], ah[mt], bl0, bl1);
                mma_bf16(acc[mt][nt], al[mt], bh0, bh1);
            }
        }
    }
    __syncwarp();

    float* Ds = (float*)zhi;
    #pragma unroll
    for (int mt = 0; mt < 2; mt++) {
        int ra = mt*16 + r0;
        #pragma unroll
        for (int nt = 0; nt < 8; nt++) {
            int cbb = 8*nt + 2*q;
            *(float2*)(Ds + ra*68 + cbb)     = make_float2(acc[mt][nt][0], acc[mt][nt][1]);
            *(float2*)(Ds + (ra+8)*68 + cbb) = make_float2(acc[mt][nt][2], acc[mt][nt][3]);
        }
    }
    __syncwarp();

    float4* ydst = (float4*)g_y2 + (size_t)g*512 + lane;
    #pragma unroll
    for (int qq = 0; qq < 16; qq++)
        ydst[qq*32] = *(float4*)(Ds + lane*68 + 4*qq);

    #pragma unroll
    for (int cp = 0; cp < 2; cp++) {
        int c = lane + 32*cp;
        float s = 0.f, sq = 0.f;
        #pragma unroll 8
        for (int ss = 0; ss < 32; ss++) {
            float x = Ds[ss*68 + c];
            s += x; sq += x*x;
        }
        atomicAdd(&ssum[c], s);
        atomicAdd(&ssq[c],  sq);
    }
    __syncthreads();
    if (tid < 64) {
        atomicAdd(&g_sum1[tid], ssum[tid]);
        atomicAdd(&g_sq1[tid],  ssq[tid]);
    }
}

// ---------------- conv3: bn1+relu, [32x64]@[64x128] + stats + max -----------
#define CV3_WLO  17408
#define CV3_ZB   34816
#define CV3_PAR  71680
#define CV3_SMEM 73216

__global__ __launch_bounds__(128) void conv3_mma(const float* __restrict__ g1p,
                                                 const float* __restrict__ be1) {
    extern __shared__ char smraw[];
    uint32_t* whi = (uint32_t*)(smraw);
    uint32_t* wlo = (uint32_t*)(smraw + CV3_WLO);
    float* ssc   = (float*)(smraw + CV3_PAR);
    float* ssh   = ssc + 64;
    float* ssum2 = ssh + 64;    // [128]
    float* ssq2  = ssum2 + 128; // [128]

    const int tid = threadIdx.x, wid = tid >> 5, lane = tid & 31;
    const int q = lane & 3, r0 = lane >> 2;
    const int g = blockIdx.x * 4 + wid;

    for (int idx = tid; idx < 32*128; idx += 128) {
        uint2 v = g_w2p[idx];
        int kk = idx >> 7, n = idx & 127;
        whi[kk*136 + n] = v.x; wlo[kk*136 + n] = v.y;
    }
    if (tid < 64) {
        const float inv = 1.0f / (float)CNT;
        float m = g_sum1[tid] * inv;
        float v = g_sq1[tid] * inv - m*m;
        float sc = g1p[tid] * rsqrtf(v + 0.001f);
        ssc[tid] = sc; ssh[tid] = be1[tid] - m*sc;
    }
    ssum2[tid] = 0.f; ssq2[tid] = 0.f;
    __syncthreads();

    uint32_t* zhi = (uint32_t*)(smraw + CV3_ZB) + wid*2304;
    uint32_t* zlo = zhi + 1152;

    {   // stage A: BN1 + relu + split from y2
        const float4* xsrc = (const float4*)g_y2 + (size_t)g*512 + lane;
        #pragma unroll
        for (int qq = 0; qq < 16; qq++) {
            float4 v = xsrc[qq*32];
            int c = qq*4;
            float z0 = fmaxf(fmaf(v.x, ssc[c+0], ssh[c+0]), 0.f);
            float z1 = fmaxf(fmaf(v.y, ssc[c+1], ssh[c+1]), 0.f);
            float z2 = fmaxf(fmaf(v.z, ssc[c+2], ssh[c+2]), 0.f);
            float z3 = fmaxf(fmaf(v.w, ssc[c+3], ssh[c+3]), 0.f);
            uint32_t h0, l0, h1, l1;
            split2(z0, z1, h0, l0); split2(z2, z3, h1, l1);
            zhi[lane*36 + 2*qq]     = h0; zhi[lane*36 + 2*qq + 1] = h1;
            zlo[lane*36 + 2*qq]     = l0; zlo[lane*36 + 2*qq + 1] = l1;
        }
    }
    __syncwarp();

    #pragma unroll 1
    for (int ch = 0; ch < 4; ch++) {       // 4 n-chunks of 32 cols
        float acc[2][4][4];
        #pragma unroll
        for (int mt = 0; mt < 2; mt++)
            #pragma unroll
            for (int ntl = 0; ntl < 4; ntl++)
                #pragma unroll
                for (int e = 0; e < 4; e++) acc[mt][ntl][e] = 0.f;

        #pragma unroll
        for (int ks = 0; ks < 4; ks++) {
            uint32_t ah[2][4], al[2][4];
            const int cb = 8*ks + q;
            #pragma unroll
            for (int mt = 0; mt < 2; mt++) {
                int ra = mt*16 + r0, rb = ra + 8;
                ah[mt][0] = zhi[ra*36 + cb];     ah[mt][1] = zhi[rb*36 + cb];
                ah[mt][2] = zhi[ra*36 + cb + 4]; ah[mt][3] = zhi[rb*36 + cb + 4];
                al[mt][0] = zlo[ra*36 + cb];     al[mt][1] = zlo[rb*36 + cb];
                al[mt][2] = zlo[ra*36 + cb + 4]; al[mt][3] = zlo[rb*36 + cb + 4];
            }
            #pragma unroll
            for (int ntl = 0; ntl < 4; ntl++) {
                int nt = ch*4 + ntl;
                int wb = cb*136 + 8*nt + r0;
                uint32_t bh0 = whi[wb], bh1 = whi[wb + 4*136];
                uint32_t bl0 = wlo[wb], bl1 = wlo[wb + 4*136];
                #pragma unroll
                for (int mt = 0; mt < 2; mt++) {
                    mma_bf16(acc[mt][ntl], ah[mt], bh0, bh1);
                    mma_bf16(acc[mt][ntl], ah[mt], bl0, bl1);
                    mma_bf16(acc[mt][ntl], al[mt], bh0, bh1);
                }
            }
        }

        #pragma unroll
        for (int ntl = 0; ntl < 4; ntl++) {
            int nt = ch*4 + ntl;
            float v00 = acc[0][ntl][0], v02 = acc[0][ntl][2];
            float v10 = acc[1][ntl][0], v12 = acc[1][ntl][2];
            float v01 = acc[0][ntl][1], v03 = acc[0][ntl][3];
            float v11 = acc[1][ntl][1], v13 = acc[1][ntl][3];
            float s0 = v00 + v02 + v10 + v12;
            float s1 = v01 + v03 + v11 + v13;
            float q0 = v00*v00 + v02*v02 + v10*v10 + v12*v12;
            float q1 = v01*v01 + v03*v03 + v11*v11 + v13*v13;
            float m0 = fmaxf(fmaxf(v00, v02), fmaxf(v10, v12));
            float m1 = fmaxf(fmaxf(v01, v03), fmaxf(v11, v13));
            #pragma unroll
            for (int off = 4; off < 32; off <<= 1) {
                s0 += __shfl_xor_sync(0xffffffffu, s0, off);
                s1 += __shfl_xor_sync(0xffffffffu, s1, off);
                q0 += __shfl_xor_sync(0xffffffffu, q0, off);
                q1 += __shfl_xor_sync(0xffffffffu, q1, off);
                m0 = fmaxf(m0, __shfl_xor_sync(0xffffffffu, m0, off));
                m1 = fmaxf(m1, __shfl_xor_sync(0xffffffffu, m1, off));
            }
            if (r0 == 0) {   // lanes 0..3
                int c = 8*nt + 2*q;
                atomicAdd(&ssum2[c],   s0); atomicAdd(&ssum2[c+1], s1);
                atomicAdd(&ssq2[c],    q0); atomicAdd(&ssq2[c+1],  q1);
                g_max3[(size_t)g*C3 + c]     = m0;
                g_max3[(size_t)g*C3 + c + 1] = m1;
            }
        }
    }
    __syncthreads();
    atomicAdd(&g_sum2[tid], ssum2[tid]);
    atomicAdd(&g_sq2[tid],  ssq2[tid]);
}

// ---------------- finalize: bn2 + relu on pooled maxes ----------------------
__global__ void finalize_kernel(const float* __restrict__ g2,
                                const float* __restrict__ be2,
                                float* __restrict__ out) {
    __shared__ float sc[C3], sh[C3];
    const int tid = threadIdx.x;
    if (tid < C3) {
        const float inv = 1.0f / (float)CNT;
        float m = g_sum2[tid] * inv;
        float v = g_sq2[tid] * inv - m*m;
        float s = g2[tid] * rsqrtf(v + 0.001f);
        sc[tid] = s; sh[tid] = be2[tid] - m*s;
    }
    __syncthreads();
    for (int i = blockIdx.x * blockDim.x + tid; i < B*P*C3; i += gridDim.x * blockDim.x) {
        int o = i & 127;
        out[OFF_NEWPTS + i] = fmaxf(fmaf(g_max3[i], sc[o], sh[o]), 0.f);
    }
}

// ---------------- launch -----------------------------------------------------
extern "C" void kernel_launch(void* const* d_in, const int* in_sizes, int n_in,
                              void* d_out, int out_size) {
    const float* xyz = (const float*)d_in[0];
    const float* pts = (const float*)d_in[1];
    const float* W0  = (const float*)d_in[2];
    const float* g0  = (const float*)d_in[4];
    const float* be0 = (const float*)d_in[5];
    const float* W1  = (const float*)d_in[6];
    const float* g1  = (const float*)d_in[8];
    const float* be1 = (const float*)d_in[9];
    const float* W2  = (const float*)d_in[10];
    const float* g2  = (const float*)d_in[12];
    const float* be2 = (const float*)d_in[13];
    float* out = (float*)d_out;

    const int smemPts = 3 * N * (int)sizeof(float);   // 49152
    cudaFuncSetAttribute(fps_kernel,   cudaFuncAttributeMaxDynamicSharedMemorySize, smemPts);
    cudaFuncSetAttribute(ballq_kernel, cudaFuncAttributeMaxDynamicSharedMemorySize, smemPts);
    cudaFuncSetAttribute(conv1_mma, cudaFuncAttributeMaxDynamicSharedMemorySize, CV1_SMEM);
    cudaFuncSetAttribute(conv2_mma, cudaFuncAttributeMaxDynamicSharedMemorySize, CV2_SMEM);
    cudaFuncSetAttribute(conv3_mma, cudaFuncAttributeMaxDynamicSharedMemorySize, CV3_SMEM);

    wsplit_kernel<<<16, 256>>>(W0, W1, W2);
    fps_kernel<<<B, FPS_T, smemPts>>>(xyz, out);
    ballq_kernel<<<dim3(16, B), 256, smemPts>>>(xyz, out);
    conv1_mma<<<(B*P)/4, 128, CV1_SMEM>>>(xyz, pts);
    conv2_mma<<<(B*P)/4, 128, CV2_SMEM>>>(g0, be0);
    conv3_mma<<<(B*P)/4, 128, CV3_SMEM>>>(g1, be1);
    finalize_kernel<<<2048, 256>>>(g2, be2, out);
}

// round 9
// speedup vs baseline: 1.2361x; 1.0194x over previous
#include <cuda_runtime.h>
#include <cuda_bf16.h>
#include <cstdint>

#define B 16
#define N 4096
#define C 64
#define P 1024      // NPOINT
#define S 32        // NSAMPLE
#define CIN0 67
#define C1 64
#define C2 64
#define C3 128
#define CNT (B*P*S) // 524288 samples per channel for BN

#define OFF_NEWXYZ 0
#define OFF_NEWPTS (B*P*3)                 // 49152
#define OFF_IDX    (B*P*3 + B*P*C3)        // 2146304

typedef unsigned long long ull;

// ---------------- mma.sync bf16 (baseline sm_80+ PTX, works on sm_103) -------
__device__ __forceinline__ void mma_bf16(float* d, const uint32_t* a, uint32_t b0, uint32_t b1) {
    asm volatile("mma.sync.aligned.m16n8k16.row.col.f32.bf16.bf16.f32 "
        "{%0,%1,%2,%3}, {%4,%5,%6,%7}, {%8,%9}, {%0,%1,%2,%3};"
        : "+f"(d[0]), "+f"(d[1]), "+f"(d[2]), "+f"(d[3])
        : "r"(a[0]), "r"(a[1]), "r"(a[2]), "r"(a[3]), "r"(b0), "r"(b1));
}

// split fp32 pair into bf16x2 (hi) and bf16x2 (residual lo); first arg = low half
__device__ __forceinline__ void split2(float a, float b, uint32_t& hi, uint32_t& lo) {
    __nv_bfloat16 ha = __float2bfloat16_rn(a);
    __nv_bfloat16 hb = __float2bfloat16_rn(b);
    __nv_bfloat162 hh = __halves2bfloat162(ha, hb);
    hi = *reinterpret_cast<uint32_t*>(&hh);
    float la = a - __bfloat162float(ha);
    float lb = b - __bfloat162float(hb);
    __nv_bfloat162 ll = __floats2bfloat162_rn(la, lb);
    lo = *reinterpret_cast<uint32_t*>(&ll);
}

// ---------------- scratch (static device memory; no allocations) ------------
__device__ float g_new_xyz[B*P*3];
__device__ int   g_idx[B*P*S];
// y layout: 16B chunks: [group][chunk 0..15][lane 0..31], chunk = 4 channels
__device__ float g_y1[(size_t)B*P*S*C1];   // 134 MB
__device__ float g_y2[(size_t)B*P*S*C2];   // 134 MB
__device__ float g_max3[(size_t)B*P*C3];   // 8 MB

__device__ float g_sum0[C1], g_sq0[C1];
__device__ float g_sum1[C2], g_sq1[C2];
__device__ float g_sum2[C3], g_sq2[C3];

// pre-split weight pair tables: .x = bf16x2 hi, .y = bf16x2 lo
__device__ uint2 g_w0p[40*64];
__device__ uint2 g_w1p[32*64];
__device__ uint2 g_w2p[32*128];

// ---------------- setup: split all weights once ------------------------------
__global__ void wsplit_kernel(const float* __restrict__ W0,
                              const float* __restrict__ W1,
                              const float* __restrict__ W2) {
    int i = blockIdx.x * blockDim.x + threadIdx.x;
    if (i < 40*64) {
        int kk = i >> 6, n = i & 63;
        float a  = (2*kk     < CIN0) ? W0[(2*kk)*C1 + n]   : 0.f;
        float bq = (2*kk + 1 < CIN0) ? W0[(2*kk+1)*C1 + n] : 0.f;
        uint32_t hi, lo; split2(a, bq, hi, lo);
        g_w0p[i] = make_uint2(hi, lo);
    }
    if (i < 32*64) {
        int kk = i >> 6, n = i & 63;
        uint32_t hi, lo;
        split2(W1[(2*kk)*C2 + n], W1[(2*kk+1)*C2 + n], hi, lo);
        g_w1p[i] = make_uint2(hi, lo);
    }
    if (i < 32*128) {
        int kk = i >> 7, n = i & 127;
        uint32_t hi, lo;
        split2(W2[(2*kk)*C3 + n], W2[(2*kk+1)*C3 + n], hi, lo);
        g_w2p[i] = make_uint2(hi, lo);
    }
}

// ---------------- FPS: one block per batch (also zeroes stats) --------------
#define FPS_T 256
#define FPS_PP (N/FPS_T)   // 16 points per thread
__global__ void fps_kernel(const float* __restrict__ xyz, float* __restrict__ out) {
    extern __shared__ float sm[];
    float* sx = sm; float* sy = sm + N; float* sz = sm + 2*N;
    __shared__ ull skey[2][FPS_T/32];

    const int b = blockIdx.x;
    const int t = threadIdx.x;
    const int lane = t & 31, w = t >> 5;

    if (b == 0) {
        if (t < C1) { g_sum0[t]=0.f; g_sq0[t]=0.f; g_sum1[t]=0.f; g_sq1[t]=0.f; }
        if (t < C3) { g_sum2[t]=0.f; g_sq2[t]=0.f; }
    }

    const float* base = xyz + (size_t)b * N * 3;
    for (int i = t; i < N; i += FPS_T) {
        sx[i] = base[i*3+0]; sy[i] = base[i*3+1]; sz[i] = base[i*3+2];
    }
    __syncthreads();

    float px[FPS_PP], py[FPS_PP], pz[FPS_PP], dd[FPS_PP];
    #pragma unroll
    for (int j = 0; j < FPS_PP; j++) {
        int i = t + j*FPS_T;
        px[j]=sx[i]; py[j]=sy[i]; pz[j]=sz[i]; dd[j]=1e10f;
    }

    int far = 0;
    for (int k = 0; k < P; k++) {
        float fx = sx[far], fy = sy[far], fz = sz[far];
        if (t == 0) {
            size_t gk = (size_t)b*P + k;
            g_new_xyz[gk*3+0]=fx; g_new_xyz[gk*3+1]=fy; g_new_xyz[gk*3+2]=fz;
            out[OFF_NEWXYZ + gk*3+0]=fx; out[OFF_NEWXYZ + gk*3+1]=fy; out[OFF_NEWXYZ + gk*3+2]=fz;
        }
        float bv = -1.f; int bi = 0x7fffffff;
        #pragma unroll
        for (int j = 0; j < FPS_PP; j++) {
            float dx = __fsub_rn(px[j], fx);
            float dy = __fsub_rn(py[j], fy);
            float dz = __fsub_rn(pz[j], fz);
            float d  = __fadd_rn(__fadd_rn(__fmul_rn(dx,dx), __fmul_rn(dy,dy)), __fmul_rn(dz,dz));
            dd[j] = fminf(dd[j], d);
            if (dd[j] > bv) { bv = dd[j]; bi = t + j*FPS_T; }
        }
        unsigned bvb = __float_as_uint(bv);
        unsigned mb  = __reduce_max_sync(0xffffffffu, bvb);
        unsigned bim = (bvb == mb) ? (unsigned)bi : 0x7fffffffu;
        unsigned bmin = __reduce_min_sync(0xffffffffu, bim);
        if (lane == 0) skey[k & 1][w] = ((ull)mb << 32) | (unsigned)(~bmin);
        __syncthreads();
        ull kb = skey[k & 1][0];
        #pragma unroll
        for (int q = 1; q < FPS_T/32; q++) {
            ull o = skey[k & 1][q];
            if (o > kb) kb = o;
        }
        far = (int)(~(unsigned)kb);
    }
}

// ---------------- Ball query: 64 centers per block, 8 per warp --------------
__global__ void ballq_kernel(const float* __restrict__ xyz, float* __restrict__ out) {
    extern __shared__ float sm[];
    float* sx = sm; float* sy = sm + N; float* sz = sm + 2*N;
    const int b = blockIdx.y;
    const int tid = threadIdx.x;
    const float* base = xyz + (size_t)b * N * 3;
    for (int i = tid; i < N; i += blockDim.x) {
        sx[i] = base[i*3+0]; sy[i] = base[i*3+1]; sz[i] = base[i*3+2];
    }
    __syncthreads();

    const int w = tid >> 5, lane = tid & 31;
    const float R2 = (float)(0.4 * 0.4);

    #pragma unroll 1
    for (int ci = 0; ci < 8; ci++) {
        const int p = blockIdx.x * 64 + w * 8 + ci;
        const int g = b * P + p;
        const float cx = g_new_xyz[g*3+0], cy = g_new_xyz[g*3+1], cz = g_new_xyz[g*3+2];

        int cnt = 0, first = -1;
        for (int basei = 0; basei < N; basei += 32) {
            int i = basei + lane;
            float dx = __fsub_rn(cx, sx[i]);
            float dy = __fsub_rn(cy, sy[i]);
            float dz = __fsub_rn(cz, sz[i]);
            float d2 = __fadd_rn(__fadd_rn(__fmul_rn(dx,dx), __fmul_rn(dy,dy)), __fmul_rn(dz,dz));
            bool pred = d2 < R2;
            unsigned m = __ballot_sync(0xffffffffu, pred);
            if (first < 0 && m) first = basei + __ffs(m) - 1;
            int rank = cnt + __popc(m & ((1u << lane) - 1u));
            if (pred && rank < S) {
                g_idx[g*S + rank] = i;
                out[OFF_IDX + g*S + rank] = (float)i;
            }
            cnt += __popc(m);
            if (cnt >= S) break;
        }
        int cntc = cnt < S ? cnt : S;
        if (lane >= cntc) {
            g_idx[g*S + lane] = first;
            out[OFF_IDX + g*S + lane] = (float)first;
        }
    }
}

// =============================================================================
// Convs: 4 groups per 128-thread block, one warp per group. Weights read
// directly from global pre-split tables in the MMA loop (L1-resident).
// =============================================================================

// ---------------- conv1: gather + (67->64), K padded to 80 (5 k-steps) ------
// smem: zbuf @0 (4 x 11264 = 45056), params @45056 (ssum64, ssq64) -> 45568
#define CV1_PAR  45056
#define CV1_SMEM 45568

__global__ __launch_bounds__(128) void conv1_mma(const float* __restrict__ xyz,
                                                 const float* __restrict__ pts) {
    extern __shared__ char smraw[];
    float* ssum = (float*)(smraw + CV1_PAR);
    float* ssq  = ssum + 64;

    const int tid = threadIdx.x, wid = tid >> 5, lane = tid & 31;
    const int q = lane & 3, r0 = lane >> 2;
    const int g = blockIdx.x * 4 + wid;
    const int b = g >> 10;

    if (tid < 64) { ssum[tid] = 0.f; ssq[tid] = 0.f; }
    __syncthreads();

    uint32_t* zhi = (uint32_t*)smraw + wid*2816;   // [32][44] words
    uint32_t* zlo = zhi + 1408;

    {   // stage A: lane = sample; gather xyz rel + pts, split, zero-pad
        const int j = g_idx[g*S + lane];
        const float* xr = xyz + ((size_t)b*N + j)*3;
        float rx = xr[0] - g_new_xyz[g*3+0];
        float ry = xr[1] - g_new_xyz[g*3+1];
        float rz = xr[2] - g_new_xyz[g*3+2];
        uint32_t hi, lo;
        split2(rx, ry, hi, lo);
        zhi[lane*44 + 0] = hi; zlo[lane*44 + 0] = lo;

        const float4* pr = (const float4*)(pts + ((size_t)b*N + j)*C);
        float carry = rz;
        int kk = 1;
        #pragma unroll
        for (int qq = 0; qq < 16; qq++) {
            float4 v = __ldg(pr + qq);
            split2(carry, v.x, hi, lo);
            zhi[lane*44 + kk] = hi; zlo[lane*44 + kk] = lo; kk++;
            split2(v.y, v.z, hi, lo);
            zhi[lane*44 + kk] = hi; zlo[lane*44 + kk] = lo; kk++;
            carry = v.w;
        }
        split2(carry, 0.f, hi, lo);
        zhi[lane*44 + 33] = hi; zlo[lane*44 + 33] = lo;
        #pragma unroll
        for (int kz = 34; kz < 40; kz++) { zhi[lane*44 + kz] = 0u; zlo[lane*44 + kz] = 0u; }
    }
    __syncwarp();

    float acc[2][8][4];
    #pragma unroll
    for (int mt = 0; mt < 2; mt++)
        #pragma unroll
        for (int nt = 0; nt < 8; nt++)
            #pragma unroll
            for (int e = 0; e < 4; e++) acc[mt][nt][e] = 0.f;

    #pragma unroll
    for (int ks = 0; ks < 5; ks++) {
        uint32_t ah[2][4], al[2][4];
        const int cb = 8*ks + q;
        #pragma unroll
        for (int mt = 0; mt < 2; mt++) {
            int ra = mt*16 + r0, rb = ra + 8;
            ah[mt][0] = zhi[ra*44 + cb];     ah[mt][1] = zhi[rb*44 + cb];
            ah[mt][2] = zhi[ra*44 + cb + 4]; ah[mt][3] = zhi[rb*44 + cb + 4];
            al[mt][0] = zlo[ra*44 + cb];     al[mt][1] = zlo[rb*44 + cb];
            al[mt][2] = zlo[ra*44 + cb + 4]; al[mt][3] = zlo[rb*44 + cb + 4];
        }
        #pragma unroll
        for (int nt = 0; nt < 8; nt++) {
            uint2 w0 = __ldg(&g_w0p[cb*64 + 8*nt + r0]);
            uint2 w1 = __ldg(&g_w0p[(cb+4)*64 + 8*nt + r0]);
            #pragma unroll
            for (int mt = 0; mt < 2; mt++) {
                mma_bf16(acc[mt][nt], ah[mt], w0.x, w1.x);
                mma_bf16(acc[mt][nt], ah[mt], w0.y, w1.y);
                mma_bf16(acc[mt][nt], al[mt], w0.x, w1.x);
            }
        }
    }
    __syncwarp();

    // D -> smem overlay (stride 68)
    float* Ds = (float*)zhi;
    #pragma unroll
    for (int mt = 0; mt < 2; mt++) {
        int ra = mt*16 + r0;
        #pragma unroll
        for (int nt = 0; nt < 8; nt++) {
            int cbb = 8*nt + 2*q;
            *(float2*)(Ds + ra*68 + cbb)     = make_float2(acc[mt][nt][0], acc[mt][nt][1]);
            *(float2*)(Ds + (ra+8)*68 + cbb) = make_float2(acc[mt][nt][2], acc[mt][nt][3]);
        }
    }
    __syncwarp();

    float4* ydst = (float4*)g_y1 + (size_t)g*512 + lane;
    #pragma unroll
    for (int qq = 0; qq < 16; qq++)
        ydst[qq*32] = *(float4*)(Ds + lane*68 + 4*qq);

    #pragma unroll
    for (int cp = 0; cp < 2; cp++) {
        int c = lane + 32*cp;
        float s = 0.f, sq = 0.f;
        #pragma unroll 8
        for (int ss = 0; ss < 32; ss++) {
            float x = Ds[ss*68 + c];
            s += x; sq += x*x;
        }
        atomicAdd(&ssum[c], s);
        atomicAdd(&ssq[c],  sq);
    }
    __syncthreads();
    if (tid < 64) {
        atomicAdd(&g_sum0[tid], ssum[tid]);
        atomicAdd(&g_sq0[tid],  ssq[tid]);
    }
}

// ---------------- conv2: bn0+relu, [32x64]@[64x64] --------------------------
// smem: zbuf @0 (4 x 9216 = 36864), params @36864 (ssc,ssh,ssum,ssq x64) -> 37888
#define CV2_PAR  36864
#define CV2_SMEM 37888

__global__ __launch_bounds__(128) void conv2_mma(const float* __restrict__ g0p,
                                                 const float* __restrict__ be0) {
    extern __shared__ char smraw[];
    float* ssc  = (float*)(smraw + CV2_PAR);
    float* ssh  = ssc + 64;
    float* ssum = ssh + 64;
    float* ssq  = ssum + 64;

    const int tid = threadIdx.x, wid = tid >> 5, lane = tid & 31;
    const int q = lane & 3, r0 = lane >> 2;
    const int g = blockIdx.x * 4 + wid;

    if (tid < 64) {
        const float inv = 1.0f / (float)CNT;
        float m = g_sum0[tid] * inv;
        float v = g_sq0[tid] * inv - m*m;
        float sc = g0p[tid] * rsqrtf(v + 0.001f);
        ssc[tid] = sc; ssh[tid] = be0[tid] - m*sc;
        ssum[tid] = 0.f; ssq[tid] = 0.f;
    }
    __syncthreads();

    uint32_t* zhi = (uint32_t*)smraw + wid*2304;   // [32][36] words
    uint32_t* zlo = zhi + 1152;

    {   // stage A: lane = sample; BN0 + relu + split
        const float4* xsrc = (const float4*)g_y1 + (size_t)g*512 + lane;
        #pragma unroll
        for (int qq = 0; qq < 16; qq++) {
            float4 v = xsrc[qq*32];
            int c = qq*4;
            float z0 = fmaxf(fmaf(v.x, ssc[c+0], ssh[c+0]), 0.f);
            float z1 = fmaxf(fmaf(v.y, ssc[c+1], ssh[c+1]), 0.f);
            float z2 = fmaxf(fmaf(v.z, ssc[c+2], ssh[c+2]), 0.f);
            float z3 = fmaxf(fmaf(v.w, ssc[c+3], ssh[c+3]), 0.f);
            uint32_t h0, l0, h1, l1;
            split2(z0, z1, h0, l0); split2(z2, z3, h1, l1);
            zhi[lane*36 + 2*qq]     = h0; zhi[lane*36 + 2*qq + 1] = h1;
            zlo[lane*36 + 2*qq]     = l0; zlo[lane*36 + 2*qq + 1] = l1;
        }
    }
    __syncwarp();

    float acc[2][8][4];
    #pragma unroll
    for (int mt = 0; mt < 2; mt++)
        #pragma unroll
        for (int nt = 0; nt < 8; nt++)
            #pragma unroll
            for (int e = 0; e < 4; e++) acc[mt][nt][e] = 0.f;

    #pragma unroll
    for (int ks = 0; ks < 4; ks++) {
        uint32_t ah[2][4], al[2][4];
        const int cb = 8*ks + q;
        #pragma unroll
        for (int mt = 0; mt < 2; mt++) {
            int ra = mt*16 + r0, rb = ra + 8;
            ah[mt][0] = zhi[ra*36 + cb];     ah[mt][1] = zhi[rb*36 + cb];
            ah[mt][2] = zhi[ra*36 + cb + 4]; ah[mt][3] = zhi[rb*36 + cb + 4];
            al[mt][0] = zlo[ra*36 + cb];     al[mt][1] = zlo[rb*36 + cb];
            al[mt][2] = zlo[ra*36 + cb + 4]; al[mt][3] = zlo[rb*36 + cb + 4];
        }
        #pragma unroll
        for (int nt = 0; nt < 8; nt++) {
            uint2 w0 = __ldg(&g_w1p[cb*64 + 8*nt + r0]);
            uint2 w1 = __ldg(&g_w1p[(cb+4)*64 + 8*nt + r0]);
            #pragma unroll
            for (int mt = 0; mt < 2; mt++) {
                mma_bf16(acc[mt][nt], ah[mt], w0.x, w1.x);
                mma_bf16(acc[mt][nt], ah[mt], w0.y, w1.y);
                mma_bf16(acc[mt][nt], al[mt], w0.x, w1.x);
            }
        }
    }
    __syncwarp();

    float* Ds = (float*)zhi;
    #pragma unroll
    for (int mt = 0; mt < 2; mt++) {
        int ra = mt*16 + r0;
        #pragma unroll
        for (int nt = 0; nt < 8; nt++) {
            int cbb = 8*nt + 2*q;
            *(float2*)(Ds + ra*68 + cbb)     = make_float2(acc[mt][nt][0], acc[mt][nt][1]);
            *(float2*)(Ds + (ra+8)*68 + cbb) = make_float2(acc[mt][nt][2], acc[mt][nt][3]);
        }
    }
    __syncwarp();

    float4* ydst = (float4*)g_y2 + (size_t)g*512 + lane;
    #pragma unroll
    for (int qq = 0; qq < 16; qq++)
        ydst[qq*32] = *(float4*)(Ds + lane*68 + 4*qq);

    #pragma unroll
    for (int cp = 0; cp < 2; cp++) {
        int c = lane + 32*cp;
        float s = 0.f, sq = 0.f;
        #pragma unroll 8
        for (int ss = 0; ss < 32; ss++) {
            float x = Ds[ss*68 + c];
            s += x; sq += x*x;
        }
        atomicAdd(&ssum[c], s);
        atomicAdd(&ssq[c],  sq);
    }
    __syncthreads();
    if (tid < 64) {
        atomicAdd(&g_sum1[tid], ssum[tid]);
        atomicAdd(&g_sq1[tid],  ssq[tid]);
    }
}

// ---------------- conv3: bn1+relu, [32x64]@[64x128] + stats + max -----------
// smem: zbuf @0 (36864), params @36864 (ssc64, ssh64, ssum128, ssq128) -> 38400
#define CV3_PAR  36864
#define CV3_SMEM 38400

__global__ __launch_bounds__(128) void conv3_mma(const float* __restrict__ g1p,
                                                 const float* __restrict__ be1) {
    extern __shared__ char smraw[];
    float* ssc   = (float*)(smraw + CV3_PAR);
    float* ssh   = ssc + 64;
    float* ssum2 = ssh + 64;    // [128]
    float* ssq2  = ssum2 + 128; // [128]

    const int tid = threadIdx.x, wid = tid >> 5, lane = tid & 31;
    const int q = lane & 3, r0 = lane >> 2;
    const int g = blockIdx.x * 4 + wid;

    if (tid < 64) {
        const float inv = 1.0f / (float)CNT;
        float m = g_sum1[tid] * inv;
        float v = g_sq1[tid] * inv - m*m;
        float sc = g1p[tid] * rsqrtf(v + 0.001f);
        ssc[tid] = sc; ssh[tid] = be1[tid] - m*sc;
    }
    ssum2[tid] = 0.f; ssq2[tid] = 0.f;
    __syncthreads();

    uint32_t* zhi = (uint32_t*)smraw + wid*2304;
    uint32_t* zlo = zhi + 1152;

    {   // stage A: BN1 + relu + split from y2
        const float4* xsrc = (const float4*)g_y2 + (size_t)g*512 + lane;
        #pragma unroll
        for (int qq = 0; qq < 16; qq++) {
            float4 v = xsrc[qq*32];
            int c = qq*4;
            float z0 = fmaxf(fmaf(v.x, ssc[c+0], ssh[c+0]), 0.f);
            float z1 = fmaxf(fmaf(v.y, ssc[c+1], ssh[c+1]), 0.f);
            float z2 = fmaxf(fmaf(v.z, ssc[c+2], ssh[c+2]), 0.f);
            float z3 = fmaxf(fmaf(v.w, ssc[c+3], ssh[c+3]), 0.f);
            uint32_t h0, l0, h1, l1;
            split2(z0, z1, h0, l0); split2(z2, z3, h1, l1);
            zhi[lane*36 + 2*qq]     = h0; zhi[lane*36 + 2*qq + 1] = h1;
            zlo[lane*36 + 2*qq]     = l0; zlo[lane*36 + 2*qq + 1] = l1;
        }
    }
    __syncwarp();

    #pragma unroll 1
    for (int ch = 0; ch < 4; ch++) {       // 4 n-chunks of 32 cols
        float acc[2][4][4];
        #pragma unroll
        for (int mt = 0; mt < 2; mt++)
            #pragma unroll
            for (int ntl = 0; ntl < 4; ntl++)
                #pragma unroll
                for (int e = 0; e < 4; e++) acc[mt][ntl][e] = 0.f;

        #pragma unroll
        for (int ks = 0; ks < 4; ks++) {
            uint32_t ah[2][4], al[2][4];
            const int cb = 8*ks + q;
            #pragma unroll
            for (int mt = 0; mt < 2; mt++) {
                int ra = mt*16 + r0, rb = ra + 8;
                ah[mt][0] = zhi[ra*36 + cb];     ah[mt][1] = zhi[rb*36 + cb];
                ah[mt][2] = zhi[ra*36 + cb + 4]; ah[mt][3] = zhi[rb*36 + cb + 4];
                al[mt][0] = zlo[ra*36 + cb];     al[mt][1] = zlo[rb*36 + cb];
                al[mt][2] = zlo[ra*36 + cb + 4]; al[mt][3] = zlo[rb*36 + cb + 4];
            }
            #pragma unroll
            for (int ntl = 0; ntl < 4; ntl++) {
                int nt = ch*4 + ntl;
                uint2 w0 = __ldg(&g_w2p[cb*128 + 8*nt + r0]);
                uint2 w1 = __ldg(&g_w2p[(cb+4)*128 + 8*nt + r0]);
                #pragma unroll
                for (int mt = 0; mt < 2; mt++) {
                    mma_bf16(acc[mt][ntl], ah[mt], w0.x, w1.x);
                    mma_bf16(acc[mt][ntl], ah[mt], w0.y, w1.y);
                    mma_bf16(acc[mt][ntl], al[mt], w0.x, w1.x);
                }
            }
        }

        #pragma unroll
        for (int ntl = 0; ntl < 4; ntl++) {
            int nt = ch*4 + ntl;
            float v00 = acc[0][ntl][0], v02 = acc[0][ntl][2];
            float v10 = acc[1][ntl][0], v12 = acc[1][ntl][2];
            float v01 = acc[0][ntl][1], v03 = acc[0][ntl][3];
            float v11 = acc[1][ntl][1], v13 = acc[1][ntl][3];
            float s0 = v00 + v02 + v10 + v12;
            float s1 = v01 + v03 + v11 + v13;
            float q0 = v00*v00 + v02*v02 + v10*v10 + v12*v12;
            float q1 = v01*v01 + v03*v03 + v11*v11 + v13*v13;
            float m0 = fmaxf(fmaxf(v00, v02), fmaxf(v10, v12));
            float m1 = fmaxf(fmaxf(v01, v03), fmaxf(v11, v13));
            #pragma unroll
            for (int off = 4; off < 32; off <<= 1) {
                s0 += __shfl_xor_sync(0xffffffffu, s0, off);
                s1 += __shfl_xor_sync(0xffffffffu, s1, off);
                q0 += __shfl_xor_sync(0xffffffffu, q0, off);
                q1 += __shfl_xor_sync(0xffffffffu, q1, off);
                m0 = fmaxf(m0, __shfl_xor_sync(0xffffffffu, m0, off));
                m1 = fmaxf(m1, __shfl_xor_sync(0xffffffffu, m1, off));
            }
            if (r0 == 0) {   // lanes 0..3
                int c = 8*nt + 2*q;
                atomicAdd(&ssum2[c],   s0); atomicAdd(&ssum2[c+1], s1);
                atomicAdd(&ssq2[c],    q0); atomicAdd(&ssq2[c+1],  q1);
                g_max3[(size_t)g*C3 + c]     = m0;
                g_max3[(size_t)g*C3 + c + 1] = m1;
            }
        }
    }
    __syncthreads();
    atomicAdd(&g_sum2[tid], ssum2[tid]);
    atomicAdd(&g_sq2[tid],  ssq2[tid]);
}

// ---------------- finalize: bn2 + relu on pooled maxes ----------------------
__global__ void finalize_kernel(const float* __restrict__ g2,
                                const float* __restrict__ be2,
                                float* __restrict__ out) {
    __shared__ float sc[C3], sh[C3];
    const int tid = threadIdx.x;
    if (tid < C3) {
        const float inv = 1.0f / (float)CNT;
        float m = g_sum2[tid] * inv;
        float v = g_sq2[tid] * inv - m*m;
        float s = g2[tid] * rsqrtf(v + 0.001f);
        sc[tid] = s; sh[tid] = be2[tid] - m*s;
    }
    __syncthreads();
    for (int i = blockIdx.x * blockDim.x + tid; i < B*P*C3; i += gridDim.x * blockDim.x) {
        int o = i & 127;
        out[OFF_NEWPTS + i] = fmaxf(fmaf(g_max3[i], sc[o], sh[o]), 0.f);
    }
}

// ---------------- launch -----------------------------------------------------
extern "C" void kernel_launch(void* const* d_in, const int* in_sizes, int n_in,
                              void* d_out, int out_size) {
    const float* xyz = (const float*)d_in[0];
    const float* pts = (const float*)d_in[1];
    const float* W0  = (const float*)d_in[2];
    const float* g0  = (const float*)d_in[4];
    const float* be0 = (const float*)d_in[5];
    const float* W1  = (const float*)d_in[6];
    const float* g1  = (const float*)d_in[8];
    const float* be1 = (const float*)d_in[9];
    const float* W2  = (const float*)d_in[10];
    const float* g2  = (const float*)d_in[12];
    const float* be2 = (const float*)d_in[13];
    float* out = (float*)d_out;

    const int smemPts = 3 * N * (int)sizeof(float);   // 49152
    cudaFuncSetAttribute(fps_kernel,   cudaFuncAttributeMaxDynamicSharedMemorySize, smemPts);
    cudaFuncSetAttribute(ballq_kernel, cudaFuncAttributeMaxDynamicSharedMemorySize, smemPts);
    cudaFuncSetAttribute(conv1_mma, cudaFuncAttributeMaxDynamicSharedMemorySize, CV1_SMEM);
    cudaFuncSetAttribute(conv2_mma, cudaFuncAttributeMaxDynamicSharedMemorySize, CV2_SMEM);
    cudaFuncSetAttribute(conv3_mma, cudaFuncAttributeMaxDynamicSharedMemorySize, CV3_SMEM);

    wsplit_kernel<<<16, 256>>>(W0, W1, W2);
    fps_kernel<<<B, FPS_T, smemPts>>>(xyz, out);
    ballq_kernel<<<dim3(16, B), 256, smemPts>>>(xyz, out);
    conv1_mma<<<(B*P)/4, 128, CV1_SMEM>>>(xyz, pts);
    conv2_mma<<<(B*P)/4, 128, CV2_SMEM>>>(g0, be0);
    conv3_mma<<<(B*P)/4, 128, CV3_SMEM>>>(g1, be1);
    finalize_kernel<<<2048, 256>>>(g2, be2, out);
}

// round 10
// speedup vs baseline: 1.2658x; 1.0240x over previous
#include <cuda_runtime.h>
#include <cuda_bf16.h>
#include <cstdint>

#define B 16
#define N 4096
#define C 64
#define P 1024      // NPOINT
#define S 32        // NSAMPLE
#define CIN0 67
#define C1 64
#define C2 64
#define C3 128
#define CNT (B*P*S) // 524288 samples per channel for BN

#define OFF_NEWXYZ 0
#define OFF_NEWPTS (B*P*3)                 // 49152
#define OFF_IDX    (B*P*3 + B*P*C3)        // 2146304

typedef unsigned long long ull;

// ---------------- mma.sync bf16 (baseline sm_80+ PTX, works on sm_103) -------
__device__ __forceinline__ void mma_bf16(float* d, const uint32_t* a, uint32_t b0, uint32_t b1) {
    asm volatile("mma.sync.aligned.m16n8k16.row.col.f32.bf16.bf16.f32 "
        "{%0,%1,%2,%3}, {%4,%5,%6,%7}, {%8,%9}, {%0,%1,%2,%3};"
        : "+f"(d[0]), "+f"(d[1]), "+f"(d[2]), "+f"(d[3])
        : "r"(a[0]), "r"(a[1]), "r"(a[2]), "r"(a[3]), "r"(b0), "r"(b1));
}

// split fp32 pair into bf16x2 (hi) and bf16x2 (residual lo); first arg = low half
__device__ __forceinline__ void split2(float a, float b, uint32_t& hi, uint32_t& lo) {
    __nv_bfloat16 ha = __float2bfloat16_rn(a);
    __nv_bfloat16 hb = __float2bfloat16_rn(b);
    __nv_bfloat162 hh = __halves2bfloat162(ha, hb);
    hi = *reinterpret_cast<uint32_t*>(&hh);
    float la = a - __bfloat162float(ha);
    float lb = b - __bfloat162float(hb);
    __nv_bfloat162 ll = __floats2bfloat162_rn(la, lb);
    lo = *reinterpret_cast<uint32_t*>(&ll);
}

// ---------------- scratch (static device memory; no allocations) ------------
__device__ float g_new_xyz[B*P*3];
__device__ int   g_idx[B*P*S];
// y layout: 16B chunks: [group][chunk 0..15][lane 0..31], chunk = 4 channels
__device__ float g_y1[(size_t)B*P*S*C1];   // 134 MB
__device__ float g_y2[(size_t)B*P*S*C2];   // 134 MB
__device__ float g_max3[(size_t)B*P*C3];   // 8 MB

__device__ float g_sum0[C1], g_sq0[C1];
__device__ float g_sum1[C2], g_sq1[C2];
__device__ float g_sum2[C3], g_sq2[C3];

// pre-split weight pair tables: .x = bf16x2 hi, .y = bf16x2 lo
__device__ uint2 g_w0p[40*64];
__device__ uint2 g_w1p[32*64];
__device__ uint2 g_w2p[32*128];

// ---------------- setup: split all weights once ------------------------------
__global__ void wsplit_kernel(const float* __restrict__ W0,
                              const float* __restrict__ W1,
                              const float* __restrict__ W2) {
    int i = blockIdx.x * blockDim.x + threadIdx.x;
    if (i < 40*64) {
        int kk = i >> 6, n = i & 63;
        float a  = (2*kk     < CIN0) ? W0[(2*kk)*C1 + n]   : 0.f;
        float bq = (2*kk + 1 < CIN0) ? W0[(2*kk+1)*C1 + n] : 0.f;
        uint32_t hi, lo; split2(a, bq, hi, lo);
        g_w0p[i] = make_uint2(hi, lo);
    }
    if (i < 32*64) {
        int kk = i >> 6, n = i & 63;
        uint32_t hi, lo;
        split2(W1[(2*kk)*C2 + n], W1[(2*kk+1)*C2 + n], hi, lo);
        g_w1p[i] = make_uint2(hi, lo);
    }
    if (i < 32*128) {
        int kk = i >> 7, n = i & 127;
        uint32_t hi, lo;
        split2(W2[(2*kk)*C3 + n], W2[(2*kk+1)*C3 + n], hi, lo);
        g_w2p[i] = make_uint2(hi, lo);
    }
}

// ---------------- FPS: one block per batch (also zeroes stats) --------------
#define FPS_T 256
#define FPS_PP (N/FPS_T)   // 16 points per thread
__global__ void fps_kernel(const float* __restrict__ xyz, float* __restrict__ out) {
    extern __shared__ float sm[];
    float* sx = sm; float* sy = sm + N; float* sz = sm + 2*N;
    __shared__ ull skey[2][FPS_T/32];

    const int b = blockIdx.x;
    const int t = threadIdx.x;
    const int lane = t & 31, w = t >> 5;

    if (b == 0) {
        if (t < C1) { g_sum0[t]=0.f; g_sq0[t]=0.f; g_sum1[t]=0.f; g_sq1[t]=0.f; }
        if (t < C3) { g_sum2[t]=0.f; g_sq2[t]=0.f; }
    }

    const float* base = xyz + (size_t)b * N * 3;
    for (int i = t; i < N; i += FPS_T) {
        sx[i] = base[i*3+0]; sy[i] = base[i*3+1]; sz[i] = base[i*3+2];
    }
    __syncthreads();

    float px[FPS_PP], py[FPS_PP], pz[FPS_PP], dd[FPS_PP];
    #pragma unroll
    for (int j = 0; j < FPS_PP; j++) {
        int i = t + j*FPS_T;
        px[j]=sx[i]; py[j]=sy[i]; pz[j]=sz[i]; dd[j]=1e10f;
    }

    int far = 0;
    for (int k = 0; k < P; k++) {
        float fx = sx[far], fy = sy[far], fz = sz[far];
        if (t == 0) {
            size_t gk = (size_t)b*P + k;
            g_new_xyz[gk*3+0]=fx; g_new_xyz[gk*3+1]=fy; g_new_xyz[gk*3+2]=fz;
            out[OFF_NEWXYZ + gk*3+0]=fx; out[OFF_NEWXYZ + gk*3+1]=fy; out[OFF_NEWXYZ + gk*3+2]=fz;
        }
        float bv = -1.f; int bi = 0x7fffffff;
        #pragma unroll
        for (int j = 0; j < FPS_PP; j++) {
            float dx = __fsub_rn(px[j], fx);
            float dy = __fsub_rn(py[j], fy);
            float dz = __fsub_rn(pz[j], fz);
            float d  = __fadd_rn(__fadd_rn(__fmul_rn(dx,dx), __fmul_rn(dy,dy)), __fmul_rn(dz,dz));
            dd[j] = fminf(dd[j], d);
            if (dd[j] > bv) { bv = dd[j]; bi = t + j*FPS_T; }
        }
        unsigned bvb = __float_as_uint(bv);
        unsigned mb  = __reduce_max_sync(0xffffffffu, bvb);
        unsigned bim = (bvb == mb) ? (unsigned)bi : 0x7fffffffu;
        unsigned bmin = __reduce_min_sync(0xffffffffu, bim);
        if (lane == 0) skey[k & 1][w] = ((ull)mb << 32) | (unsigned)(~bmin);
        __syncthreads();
        ull kb = skey[k & 1][0];
        #pragma unroll
        for (int q = 1; q < FPS_T/32; q++) {
            ull o = skey[k & 1][q];
            if (o > kb) kb = o;
        }
        far = (int)(~(unsigned)kb);
    }
}

// ---------------- Ball query: 64 centers per block, 8 per warp --------------
__global__ void ballq_kernel(const float* __restrict__ xyz, float* __restrict__ out) {
    extern __shared__ float sm[];
    float* sx = sm; float* sy = sm + N; float* sz = sm + 2*N;
    const int b = blockIdx.y;
    const int tid = threadIdx.x;
    const float* base = xyz + (size_t)b * N * 3;
    for (int i = tid; i < N; i += blockDim.x) {
        sx[i] = base[i*3+0]; sy[i] = base[i*3+1]; sz[i] = base[i*3+2];
    }
    __syncthreads();

    const int w = tid >> 5, lane = tid & 31;
    const float R2 = (float)(0.4 * 0.4);

    #pragma unroll 1
    for (int ci = 0; ci < 8; ci++) {
        const int p = blockIdx.x * 64 + w * 8 + ci;
        const int g = b * P + p;
        const float cx = g_new_xyz[g*3+0], cy = g_new_xyz[g*3+1], cz = g_new_xyz[g*3+2];

        int cnt = 0, first = -1;
        for (int basei = 0; basei < N; basei += 32) {
            int i = basei + lane;
            float dx = __fsub_rn(cx, sx[i]);
            float dy = __fsub_rn(cy, sy[i]);
            float dz = __fsub_rn(cz, sz[i]);
            float d2 = __fadd_rn(__fadd_rn(__fmul_rn(dx,dx), __fmul_rn(dy,dy)), __fmul_rn(dz,dz));
            bool pred = d2 < R2;
            unsigned m = __ballot_sync(0xffffffffu, pred);
            if (first < 0 && m) first = basei + __ffs(m) - 1;
            int rank = cnt + __popc(m & ((1u << lane) - 1u));
            if (pred && rank < S) {
                g_idx[g*S + rank] = i;
                out[OFF_IDX + g*S + rank] = (float)i;
            }
            cnt += __popc(m);
            if (cnt >= S) break;
        }
        int cntc = cnt < S ? cnt : S;
        if (lane >= cntc) {
            g_idx[g*S + lane] = first;
            out[OFF_IDX + g*S + lane] = (float)first;
        }
    }
}

// =============================================================================
// Convs: 4 groups per 128-thread block, one warp per group. Weights read
// directly from global pre-split tables in the MMA loop (L1-resident).
// =============================================================================

// ---------------- conv1: gather + (67->64), K padded to 80 (5 k-steps) ------
// smem: zbuf @0 (4 x 11264 = 45056), params @45056 (ssum64, ssq64) -> 45568
#define CV1_PAR  45056
#define CV1_SMEM 45568

__global__ __launch_bounds__(128, 4) void conv1_mma(const float* __restrict__ xyz,
                                                    const float* __restrict__ pts) {
    extern __shared__ char smraw[];
    float* ssum = (float*)(smraw + CV1_PAR);
    float* ssq  = ssum + 64;

    const int tid = threadIdx.x, wid = tid >> 5, lane = tid & 31;
    const int q = lane & 3, r0 = lane >> 2;
    const int g = blockIdx.x * 4 + wid;
    const int b = g >> 10;

    if (tid < 64) { ssum[tid] = 0.f; ssq[tid] = 0.f; }
    __syncthreads();

    uint32_t* zhi = (uint32_t*)smraw + wid*2816;   // [32][44] words
    uint32_t* zlo = zhi + 1408;

    {   // stage A: coalesced gather. Half-warp loads one sample row per pass.
        const int j = g_idx[g*S + lane];           // own sample index
        const float* xr = xyz + ((size_t)b*N + j)*3;
        float rx = xr[0] - g_new_xyz[g*3+0];
        float ry = xr[1] - g_new_xyz[g*3+1];
        float rz = xr[2] - g_new_xyz[g*3+2];
        uint32_t hi, lo;
        split2(rx, ry, hi, lo);                    // own row kk=0
        zhi[lane*44 + 0] = hi; zlo[lane*44 + 0] = lo;
        #pragma unroll
        for (int kz = 34; kz < 40; kz++) { zhi[lane*44 + kz] = 0u; zlo[lane*44 + kz] = 0u; }

        const int half = lane >> 4;                // which row of the pair
        const int c = lane & 15;                   // float4 chunk within row
        #pragma unroll
        for (int p = 0; p < 16; p++) {
            int s = 2*p + half;
            int rowj  = __shfl_sync(0xffffffffu, j,  s);
            float rzs = __shfl_sync(0xffffffffu, rz, s);
            float4 v = __ldg((const float4*)(pts + ((size_t)b*N + rowj)*C) + c);
            float pw = __shfl_up_sync(0xffffffffu, v.w, 1, 16);
            float prev = (c == 0) ? rzs : pw;
            uint32_t h0, l0, h1, l1;
            split2(prev, v.x, h0, l0);             // channels (4c+2, 4c+3) -> kk=2c+1
            split2(v.y,  v.z, h1, l1);             // channels (4c+4, 4c+5) -> kk=2c+2
            zhi[s*44 + 2*c + 1] = h0; zhi[s*44 + 2*c + 2] = h1;
            zlo[s*44 + 2*c + 1] = l0; zlo[s*44 + 2*c + 2] = l1;
            if (c == 15) {                         // channel 66 -> kk=33 (pad hi)
                uint32_t h2, l2;
                split2(v.w, 0.f, h2, l2);
                zhi[s*44 + 33] = h2; zlo[s*44 + 33] = l2;
            }
        }
    }
    __syncwarp();

    float acc[2][8][4];
    #pragma unroll
    for (int mt = 0; mt < 2; mt++)
        #pragma unroll
        for (int nt = 0; nt < 8; nt++)
            #pragma unroll
            for (int e = 0; e < 4; e++) acc[mt][nt][e] = 0.f;

    #pragma unroll
    for (int ks = 0; ks < 5; ks++) {
        uint32_t ah[2][4], al[2][4];
        const int cb = 8*ks + q;
        #pragma unroll
        for (int mt = 0; mt < 2; mt++) {
            int ra = mt*16 + r0, rb = ra + 8;
            ah[mt][0] = zhi[ra*44 + cb];     ah[mt][1] = zhi[rb*44 + cb];
            ah[mt][2] = zhi[ra*44 + cb + 4]; ah[mt][3] = zhi[rb*44 + cb + 4];
            al[mt][0] = zlo[ra*44 + cb];     al[mt][1] = zlo[rb*44 + cb];
            al[mt][2] = zlo[ra*44 + cb + 4]; al[mt][3] = zlo[rb*44 + cb + 4];
        }
        #pragma unroll
        for (int nt = 0; nt < 8; nt++) {
            uint2 w0 = __ldg(&g_w0p[cb*64 + 8*nt + r0]);
            uint2 w1 = __ldg(&g_w0p[(cb+4)*64 + 8*nt + r0]);
            #pragma unroll
            for (int mt = 0; mt < 2; mt++) {
                mma_bf16(acc[mt][nt], ah[mt], w0.x, w1.x);
                mma_bf16(acc[mt][nt], ah[mt], w0.y, w1.y);
                mma_bf16(acc[mt][nt], al[mt], w0.x, w1.x);
            }
        }
    }
    __syncwarp();

    // D -> smem overlay (stride 68)
    float* Ds = (float*)zhi;
    #pragma unroll
    for (int mt = 0; mt < 2; mt++) {
        int ra = mt*16 + r0;
        #pragma unroll
        for (int nt = 0; nt < 8; nt++) {
            int cbb = 8*nt + 2*q;
            *(float2*)(Ds + ra*68 + cbb)     = make_float2(acc[mt][nt][0], acc[mt][nt][1]);
            *(float2*)(Ds + (ra+8)*68 + cbb) = make_float2(acc[mt][nt][2], acc[mt][nt][3]);
        }
    }
    __syncwarp();

    float4* ydst = (float4*)g_y1 + (size_t)g*512 + lane;
    #pragma unroll
    for (int qq = 0; qq < 16; qq++)
        ydst[qq*32] = *(float4*)(Ds + lane*68 + 4*qq);

    #pragma unroll
    for (int cp = 0; cp < 2; cp++) {
        int c = lane + 32*cp;
        float s = 0.f, sq = 0.f;
        #pragma unroll 8
        for (int ss = 0; ss < 32; ss++) {
            float x = Ds[ss*68 + c];
            s += x; sq += x*x;
        }
        atomicAdd(&ssum[c], s);
        atomicAdd(&ssq[c],  sq);
    }
    __syncthreads();
    if (tid < 64) {
        atomicAdd(&g_sum0[tid], ssum[tid]);
        atomicAdd(&g_sq0[tid],  ssq[tid]);
    }
}

// ---------------- conv2: bn0+relu, [32x64]@[64x64] --------------------------
// smem: zbuf @0 (4 x 9216 = 36864), params @36864 (ssc,ssh,ssum,ssq x64) -> 37888
#define CV2_PAR  36864
#define CV2_SMEM 37888

__global__ __launch_bounds__(128, 4) void conv2_mma(const float* __restrict__ g0p,
                                                    const float* __restrict__ be0) {
    extern __shared__ char smraw[];
    float* ssc  = (float*)(smraw + CV2_PAR);
    float* ssh  = ssc + 64;
    float* ssum = ssh + 64;
    float* ssq  = ssum + 64;

    const int tid = threadIdx.x, wid = tid >> 5, lane = tid & 31;
    const int q = lane & 3, r0 = lane >> 2;
    const int g = blockIdx.x * 4 + wid;

    if (tid < 64) {
        const float inv = 1.0f / (float)CNT;
        float m = g_sum0[tid] * inv;
        float v = g_sq0[tid] * inv - m*m;
        float sc = g0p[tid] * rsqrtf(v + 0.001f);
        ssc[tid] = sc; ssh[tid] = be0[tid] - m*sc;
        ssum[tid] = 0.f; ssq[tid] = 0.f;
    }
    __syncthreads();

    uint32_t* zhi = (uint32_t*)smraw + wid*2304;   // [32][36] words
    uint32_t* zlo = zhi + 1152;

    {   // stage A: lane = sample; BN0 + relu + split
        const float4* xsrc = (const float4*)g_y1 + (size_t)g*512 + lane;
        #pragma unroll
        for (int qq = 0; qq < 16; qq++) {
            float4 v = xsrc[qq*32];
            int c = qq*4;
            float z0 = fmaxf(fmaf(v.x, ssc[c+0], ssh[c+0]), 0.f);
            float z1 = fmaxf(fmaf(v.y, ssc[c+1], ssh[c+1]), 0.f);
            float z2 = fmaxf(fmaf(v.z, ssc[c+2], ssh[c+2]), 0.f);
            float z3 = fmaxf(fmaf(v.w, ssc[c+3], ssh[c+3]), 0.f);
            uint32_t h0, l0, h1, l1;
            split2(z0, z1, h0, l0); split2(z2, z3, h1, l1);
            zhi[lane*36 + 2*qq]     = h0; zhi[lane*36 + 2*qq + 1] = h1;
            zlo[lane*36 + 2*qq]     = l0; zlo[lane*36 + 2*qq + 1] = l1;
        }
    }
    __syncwarp();

    float acc[2][8][4];
    #pragma unroll
    for (int mt = 0; mt < 2; mt++)
        #pragma unroll
        for (int nt = 0; nt < 8; nt++)
            #pragma unroll
            for (int e = 0; e < 4; e++) acc[mt][nt][e] = 0.f;

    #pragma unroll
    for (int ks = 0; ks < 4; ks++) {
        uint32_t ah[2][4], al[2][4];
        const int cb = 8*ks + q;
        #pragma unroll
        for (int mt = 0; mt < 2; mt++) {
            int ra = mt*16 + r0, rb = ra + 8;
            ah[mt][0] = zhi[ra*36 + cb];     ah[mt][1] = zhi[rb*36 + cb];
            ah[mt][2] = zhi[ra*36 + cb + 4]; ah[mt][3] = zhi[rb*36 + cb + 4];
            al[mt][0] = zlo[ra*36 + cb];     al[mt][1] = zlo[rb*36 + cb];
            al[mt][2] = zlo[ra*36 + cb + 4]; al[mt][3] = zlo[rb*36 + cb + 4];
        }
        #pragma unroll
        for (int nt = 0; nt < 8; nt++) {
            uint2 w0 = __ldg(&g_w1p[cb*64 + 8*nt + r0]);
            uint2 w1 = __ldg(&g_w1p[(cb+4)*64 + 8*nt + r0]);
            #pragma unroll
            for (int mt = 0; mt < 2; mt++) {
                mma_bf16(acc[mt][nt], ah[mt], w0.x, w1.x);
                mma_bf16(acc[mt][nt], ah[mt], w0.y, w1.y);
                mma_bf16(acc[mt][nt], al[mt], w0.x, w1.x);
            }
        }
    }
    __syncwarp();

    float* Ds = (float*)zhi;
    #pragma unroll
    for (int mt = 0; mt < 2; mt++) {
        int ra = mt*16 + r0;
        #pragma unroll
        for (int nt = 0; nt < 8; nt++) {
            int cbb = 8*nt + 2*q;
            *(float2*)(Ds + ra*68 + cbb)     = make_float2(acc[mt][nt][0], acc[mt][nt][1]);
            *(float2*)(Ds + (ra+8)*68 + cbb) = make_float2(acc[mt][nt][2], acc[mt][nt][3]);
        }
    }
    __syncwarp();

    float4* ydst = (float4*)g_y2 + (size_t)g*512 + lane;
    #pragma unroll
    for (int qq = 0; qq < 16; qq++)
        ydst[qq*32] = *(float4*)(Ds + lane*68 + 4*qq);

    #pragma unroll
    for (int cp = 0; cp < 2; cp++) {
        int c = lane + 32*cp;
        float s = 0.f, sq = 0.f;
        #pragma unroll 8
        for (int ss = 0; ss < 32; ss++) {
            float x = Ds[ss*68 + c];
            s += x; sq += x*x;
        }
        atomicAdd(&ssum[c], s);
        atomicAdd(&ssq[c],  sq);
    }
    __syncthreads();
    if (tid < 64) {
        atomicAdd(&g_sum1[tid], ssum[tid]);
        atomicAdd(&g_sq1[tid],  ssq[tid]);
    }
}

// ---------------- conv3: bn1+relu, [32x64]@[64x128] + stats + max -----------
// smem: zbuf @0 (36864), params @36864 (ssc64, ssh64, ssum128, ssq128) -> 38400
#define CV3_PAR  36864
#define CV3_SMEM 38400

__global__ __launch_bounds__(128, 4) void conv3_mma(const float* __restrict__ g1p,
                                                    const float* __restrict__ be1) {
    extern __shared__ char smraw[];
    float* ssc   = (float*)(smraw + CV3_PAR);
    float* ssh   = ssc + 64;
    float* ssum2 = ssh + 64;    // [128]
    float* ssq2  = ssum2 + 128; // [128]

    const int tid = threadIdx.x, wid = tid >> 5, lane = tid & 31;
    const int q = lane & 3, r0 = lane >> 2;
    const int g = blockIdx.x * 4 + wid;

    if (tid < 64) {
        const float inv = 1.0f / (float)CNT;
        float m = g_sum1[tid] * inv;
        float v = g_sq1[tid] * inv - m*m;
        float sc = g1p[tid] * rsqrtf(v + 0.001f);
        ssc[tid] = sc; ssh[tid] = be1[tid] - m*sc;
    }
    ssum2[tid] = 0.f; ssq2[tid] = 0.f;
    __syncthreads();

    uint32_t* zhi = (uint32_t*)smraw + wid*2304;
    uint32_t* zlo = zhi + 1152;

    {   // stage A: BN1 + relu + split from y2
        const float4* xsrc = (const float4*)g_y2 + (size_t)g*512 + lane;
        #pragma unroll
        for (int qq = 0; qq < 16; qq++) {
            float4 v = xsrc[qq*32];
            int c = qq*4;
            float z0 = fmaxf(fmaf(v.x, ssc[c+0], ssh[c+0]), 0.f);
            float z1 = fmaxf(fmaf(v.y, ssc[c+1], ssh[c+1]), 0.f);
            float z2 = fmaxf(fmaf(v.z, ssc[c+2], ssh[c+2]), 0.f);
            float z3 = fmaxf(fmaf(v.w, ssc[c+3], ssh[c+3]), 0.f);
            uint32_t h0, l0, h1, l1;
            split2(z0, z1, h0, l0); split2(z2, z3, h1, l1);
            zhi[lane*36 + 2*qq]     = h0; zhi[lane*36 + 2*qq + 1] = h1;
            zlo[lane*36 + 2*qq]     = l0; zlo[lane*36 + 2*qq + 1] = l1;
        }
    }
    __syncwarp();

    #pragma unroll 1
    for (int ch = 0; ch < 4; ch++) {       // 4 n-chunks of 32 cols
        float acc[2][4][4];
        #pragma unroll
        for (int mt = 0; mt < 2; mt++)
            #pragma unroll
            for (int ntl = 0; ntl < 4; ntl++)
                #pragma unroll
                for (int e = 0; e < 4; e++) acc[mt][ntl][e] = 0.f;

        #pragma unroll
        for (int ks = 0; ks < 4; ks++) {
            uint32_t ah[2][4], al[2][4];
            const int cb = 8*ks + q;
            #pragma unroll
            for (int mt = 0; mt < 2; mt++) {
                int ra = mt*16 + r0, rb = ra + 8;
                ah[mt][0] = zhi[ra*36 + cb];     ah[mt][1] = zhi[rb*36 + cb];
                ah[mt][2] = zhi[ra*36 + cb + 4]; ah[mt][3] = zhi[rb*36 + cb + 4];
                al[mt][0] = zlo[ra*36 + cb];     al[mt][1] = zlo[rb*36 + cb];
                al[mt][2] = zlo[ra*36 + cb + 4]; al[mt][3] = zlo[rb*36 + cb + 4];
            }
            #pragma unroll
            for (int ntl = 0; ntl < 4; ntl++) {
                int nt = ch*4 + ntl;
                uint2 w0 = __ldg(&g_w2p[cb*128 + 8*nt + r0]);
                uint2 w1 = __ldg(&g_w2p[(cb+4)*128 + 8*nt + r0]);
                #pragma unroll
                for (int mt = 0; mt < 2; mt++) {
                    mma_bf16(acc[mt][ntl], ah[mt], w0.x, w1.x);
                    mma_bf16(acc[mt][ntl], ah[mt], w0.y, w1.y);
                    mma_bf16(acc[mt][ntl], al[mt], w0.x, w1.x);
                }
            }
        }

        #pragma unroll
        for (int ntl = 0; ntl < 4; ntl++) {
            int nt = ch*4 + ntl;
            float v00 = acc[0][ntl][0], v02 = acc[0][ntl][2];
            float v10 = acc[1][ntl][0], v12 = acc[1][ntl][2];
            float v01 = acc[0][ntl][1], v03 = acc[0][ntl][3];
            float v11 = acc[1][ntl][1], v13 = acc[1][ntl][3];
            float s0 = v00 + v02 + v10 + v12;
            float s1 = v01 + v03 + v11 + v13;
            float q0 = v00*v00 + v02*v02 + v10*v10 + v12*v12;
            float q1 = v01*v01 + v03*v03 + v11*v11 + v13*v13;
            float m0 = fmaxf(fmaxf(v00, v02), fmaxf(v10, v12));
            float m1 = fmaxf(fmaxf(v01, v03), fmaxf(v11, v13));
            #pragma unroll
            for (int off = 4; off < 32; off <<= 1) {
                s0 += __shfl_xor_sync(0xffffffffu, s0, off);
                s1 += __shfl_xor_sync(0xffffffffu, s1, off);
                q0 += __shfl_xor_sync(0xffffffffu, q0, off);
                q1 += __shfl_xor_sync(0xffffffffu, q1, off);
                m0 = fmaxf(m0, __shfl_xor_sync(0xffffffffu, m0, off));
                m1 = fmaxf(m1, __shfl_xor_sync(0xffffffffu, m1, off));
            }
            if (r0 == 0) {   // lanes 0..3
                int c = 8*nt + 2*q;
                atomicAdd(&ssum2[c],   s0); atomicAdd(&ssum2[c+1], s1);
                atomicAdd(&ssq2[c],    q0); atomicAdd(&ssq2[c+1],  q1);
                g_max3[(size_t)g*C3 + c]     = m0;
                g_max3[(size_t)g*C3 + c + 1] = m1;
            }
        }
    }
    __syncthreads();
    atomicAdd(&g_sum2[tid], ssum2[tid]);
    atomicAdd(&g_sq2[tid],  ssq2[tid]);
}

// ---------------- finalize: bn2 + relu on pooled maxes ----------------------
__global__ void finalize_kernel(const float* __restrict__ g2,
                                const float* __restrict__ be2,
                                float* __restrict__ out) {
    __shared__ float sc[C3], sh[C3];
    const int tid = threadIdx.x;
    if (tid < C3) {
        const float inv = 1.0f / (float)CNT;
        float m = g_sum2[tid] * inv;
        float v = g_sq2[tid] * inv - m*m;
        float s = g2[tid] * rsqrtf(v + 0.001f);
        sc[tid] = s; sh[tid] = be2[tid] - m*s;
    }
    __syncthreads();
    for (int i = blockIdx.x * blockDim.x + tid; i < B*P*C3; i += gridDim.x * blockDim.x) {
        int o = i & 127;
        out[OFF_NEWPTS + i] = fmaxf(fmaf(g_max3[i], sc[o], sh[o]), 0.f);
    }
}

// ---------------- launch -----------------------------------------------------
extern "C" void kernel_launch(void* const* d_in, const int* in_sizes, int n_in,
                              void* d_out, int out_size) {
    const float* xyz = (const float*)d_in[0];
    const float* pts = (const float*)d_in[1];
    const float* W0  = (const float*)d_in[2];
    const float* g0  = (const float*)d_in[4];
    const float* be0 = (const float*)d_in[5];
    const float* W1  = (const float*)d_in[6];
    const float* g1  = (const float*)d_in[8];
    const float* be1 = (const float*)d_in[9];
    const float* W2  = (const float*)d_in[10];
    const float* g2  = (const float*)d_in[12];
    const float* be2 = (const float*)d_in[13];
    float* out = (float*)d_out;

    const int smemPts = 3 * N * (int)sizeof(float);   // 49152
    cudaFuncSetAttribute(fps_kernel,   cudaFuncAttributeMaxDynamicSharedMemorySize, smemPts);
    cudaFuncSetAttribute(ballq_kernel, cudaFuncAttributeMaxDynamicSharedMemorySize, smemPts);
    cudaFuncSetAttribute(conv1_mma, cudaFuncAttributeMaxDynamicSharedMemorySize, CV1_SMEM);
    cudaFuncSetAttribute(conv2_mma, cudaFuncAttributeMaxDynamicSharedMemorySize, CV2_SMEM);
    cudaFuncSetAttribute(conv3_mma, cudaFuncAttributeMaxDynamicSharedMemorySize, CV3_SMEM);

    wsplit_kernel<<<16, 256>>>(W0, W1, W2);
    fps_kernel<<<B, FPS_T, smemPts>>>(xyz, out);
    ballq_kernel<<<dim3(16, B), 256, smemPts>>>(xyz, out);
    conv1_mma<<<(B*P)/4, 128, CV1_SMEM>>>(xyz, pts);
    conv2_mma<<<(B*P)/4, 128, CV2_SMEM>>>(g0, be0);
    conv3_mma<<<(B*P)/4, 128, CV3_SMEM>>>(g1, be1);
    finalize_kernel<<<2048, 256>>>(g2, be2, out);
}